// round 2
// baseline (speedup 1.0000x reference)
#include <cuda_runtime.h>
#include <math.h>

#define BB   2
#define SS   2048
#define HH   768
#define NHH  12
#define DHH  64
#define FFF  3072
#define ADD  64
#define MM   (BB*SS)   // 4096

// ---------------- scratch (static device globals; no allocation) ----------
__device__ float g_q[MM*HH];
__device__ float g_k[MM*HH];
__device__ float g_v[MM*HH];
__device__ float g_attn[MM*HH];
__device__ float g_adpt[MM*ADD];
__device__ float g_attn2[MM*HH];
__device__ float g_inter[MM*FFF];
__device__ float g_y[MM*HH];

__device__ __forceinline__ float gelu_exact(float x) {
    return 0.5f * x * (1.0f + erff(x * 0.70710678118654752f));
}

// ---------------------------------------------------------------------------
// C[M,N] = A[M,K] * B[N,K]^T + bias  (+ epilogue)
// EPI: 0 = bias, 1 = bias+gelu, 2 = bias+residual
// BM=BN=128, BK=8, 256 threads, 8x8 per-thread tile.
// Requires M % 128 == 0, K % 8 == 0. N guarded.
// ---------------------------------------------------------------------------
template<int EPI>
__global__ void __launch_bounds__(256) sgemm_nt(
    int M, int N, int K,
    const float* __restrict__ A, const float* __restrict__ B,
    const float* __restrict__ bias, const float* __restrict__ res,
    float* __restrict__ C)
{
    __shared__ float As[8][128];
    __shared__ float Bs[8][128];
    int t  = threadIdx.x;
    int tx = t & 15, ty = t >> 4;
    int rowBase = blockIdx.y * 128;
    int colBase = blockIdx.x * 128;
    int lr = t >> 1;          // 0..127
    int lk = (t & 1) * 4;     // 0 or 4

    float acc[8][8];
    #pragma unroll
    for (int i = 0; i < 8; i++)
        #pragma unroll
        for (int j = 0; j < 8; j++) acc[i][j] = 0.f;

    const float* Ap = A + (size_t)(rowBase + lr) * K + lk;
    int brow = colBase + lr;
    const float* Bp = B + (size_t)brow * K + lk;
    bool bok = (brow < N);

    for (int k0 = 0; k0 < K; k0 += 8) {
        float4 a4 = *(const float4*)(Ap + k0);
        float4 b4 = make_float4(0.f, 0.f, 0.f, 0.f);
        if (bok) b4 = *(const float4*)(Bp + k0);
        As[lk + 0][lr] = a4.x; As[lk + 1][lr] = a4.y;
        As[lk + 2][lr] = a4.z; As[lk + 3][lr] = a4.w;
        Bs[lk + 0][lr] = b4.x; Bs[lk + 1][lr] = b4.y;
        Bs[lk + 2][lr] = b4.z; Bs[lk + 3][lr] = b4.w;
        __syncthreads();
        #pragma unroll
        for (int kk = 0; kk < 8; kk++) {
            float4 a0 = *(const float4*)&As[kk][ty * 8];
            float4 a1 = *(const float4*)&As[kk][ty * 8 + 4];
            float4 b0 = *(const float4*)&Bs[kk][tx * 8];
            float4 b1 = *(const float4*)&Bs[kk][tx * 8 + 4];
            float av[8] = {a0.x, a0.y, a0.z, a0.w, a1.x, a1.y, a1.z, a1.w};
            float bv[8] = {b0.x, b0.y, b0.z, b0.w, b1.x, b1.y, b1.z, b1.w};
            #pragma unroll
            for (int i = 0; i < 8; i++)
                #pragma unroll
                for (int j = 0; j < 8; j++)
                    acc[i][j] += av[i] * bv[j];
        }
        __syncthreads();
    }

    #pragma unroll
    for (int i = 0; i < 8; i++) {
        int r = rowBase + ty * 8 + i;
        #pragma unroll
        for (int j = 0; j < 8; j++) {
            int c = colBase + tx * 8 + j;
            if (c < N) {
                float vv = acc[i][j] + bias[c];
                if (EPI == 1) vv = gelu_exact(vv);
                if (EPI == 2) vv += res[(size_t)r * N + c];
                C[(size_t)r * N + c] = vv;
            }
        }
    }
}

// ---------------------------------------------------------------------------
// Flash attention, fp32. BQ=64 query rows / block, BK=32 keys / iter, D=64.
// grid = (S/BQ, B*NH), 256 threads (16x16).
// S-tile: each thread 4 rows x 2 cols. O-tile: each thread 4 rows x 4 cols.
// ---------------------------------------------------------------------------
#define BQ  64
#define BKT 32

__global__ void __launch_bounds__(256) flash_attn_kernel(
    const float* __restrict__ Q, const float* __restrict__ K,
    const float* __restrict__ V, const float* __restrict__ mask,
    float* __restrict__ out)
{
    __shared__ float Qs[BQ][DHH + 1];     // 64 x 65
    __shared__ float Kts[DHH][BKT + 1];   // 64 x 33 (K transposed)
    __shared__ float Vs[BKT][DHH];        // 32 x 64
    __shared__ float Ps[BQ][BKT + 1];     // 64 x 33

    int t  = threadIdx.x;
    int tx = t & 15, ty = t >> 4;
    int bh = blockIdx.y;
    int b  = bh / NHH, h = bh % NHH;
    int q0 = blockIdx.x * BQ;
    const float scale = 0.125f;   // 1/sqrt(64)

    // load Q tile, pre-scaled
    {
        const float* Qbase = Q + ((size_t)(b * SS + q0)) * HH + h * DHH;
        for (int i = t; i < BQ * (DHH / 4); i += 256) {
            int r = i >> 4;
            int c = (i & 15) * 4;
            float4 v4 = *(const float4*)(Qbase + (size_t)r * HH + c);
            Qs[r][c + 0] = v4.x * scale; Qs[r][c + 1] = v4.y * scale;
            Qs[r][c + 2] = v4.z * scale; Qs[r][c + 3] = v4.w * scale;
        }
    }

    float mreg[4], lreg[4], O[4][4];
    #pragma unroll
    for (int i = 0; i < 4; i++) {
        mreg[i] = -1e30f; lreg[i] = 0.f;
        #pragma unroll
        for (int j = 0; j < 4; j++) O[i][j] = 0.f;
    }

    const float* Kb = K + ((size_t)(b * SS)) * HH + h * DHH;
    const float* Vb = V + ((size_t)(b * SS)) * HH + h * DHH;
    const float* Mb = mask + (size_t)b * SS;

    for (int kb = 0; kb < SS; kb += BKT) {
        // load K (transposed) and V tiles
        for (int i = t; i < BKT * (DHH / 4); i += 256) {
            int r = i >> 4;
            int c = (i & 15) * 4;
            float4 kv = *(const float4*)(Kb + (size_t)(kb + r) * HH + c);
            Kts[c + 0][r] = kv.x; Kts[c + 1][r] = kv.y;
            Kts[c + 2][r] = kv.z; Kts[c + 3][r] = kv.w;
            float4 vv = *(const float4*)(Vb + (size_t)(kb + r) * HH + c);
            *(float4*)&Vs[r][c] = vv;
        }
        __syncthreads();

        // S = Q * K^T (scaled already via Q)
        float s[4][2];
        #pragma unroll
        for (int i = 0; i < 4; i++) { s[i][0] = 0.f; s[i][1] = 0.f; }
        #pragma unroll 8
        for (int d = 0; d < DHH; d++) {
            float b0 = Kts[d][tx * 2 + 0];
            float b1 = Kts[d][tx * 2 + 1];
            #pragma unroll
            for (int i = 0; i < 4; i++) {
                float a = Qs[ty * 4 + i][d];
                s[i][0] += a * b0;
                s[i][1] += a * b1;
            }
        }
        float mk0 = Mb[kb + tx * 2 + 0];
        float mk1 = Mb[kb + tx * 2 + 1];

        // online softmax update (row = 16 threads sharing ty, shfl width 16)
        #pragma unroll
        for (int i = 0; i < 4; i++) {
            float s0 = s[i][0] + mk0;
            float s1 = s[i][1] + mk1;
            float rmax = fmaxf(s0, s1);
            #pragma unroll
            for (int off = 8; off >= 1; off >>= 1)
                rmax = fmaxf(rmax, __shfl_xor_sync(0xffffffffu, rmax, off, 16));
            float newm  = fmaxf(mreg[i], rmax);
            float alpha = __expf(mreg[i] - newm);
            float p0 = __expf(s0 - newm);
            float p1 = __expf(s1 - newm);
            float rsum = p0 + p1;
            #pragma unroll
            for (int off = 8; off >= 1; off >>= 1)
                rsum += __shfl_xor_sync(0xffffffffu, rsum, off, 16);
            lreg[i] = lreg[i] * alpha + rsum;
            mreg[i] = newm;
            #pragma unroll
            for (int j = 0; j < 4; j++) O[i][j] *= alpha;
            Ps[ty * 4 + i][tx * 2 + 0] = p0;
            Ps[ty * 4 + i][tx * 2 + 1] = p1;
        }
        __syncthreads();

        // O += P * V
        #pragma unroll 4
        for (int k = 0; k < BKT; k++) {
            float b0 = Vs[k][tx * 4 + 0];
            float b1 = Vs[k][tx * 4 + 1];
            float b2 = Vs[k][tx * 4 + 2];
            float b3 = Vs[k][tx * 4 + 3];
            #pragma unroll
            for (int i = 0; i < 4; i++) {
                float a = Ps[ty * 4 + i][k];
                O[i][0] += a * b0; O[i][1] += a * b1;
                O[i][2] += a * b2; O[i][3] += a * b3;
            }
        }
        __syncthreads();
    }

    float* Ob = out + ((size_t)(b * SS + q0)) * HH + h * DHH;
    #pragma unroll
    for (int i = 0; i < 4; i++) {
        float inv = 1.0f / lreg[i];
        float4 v4 = make_float4(O[i][0] * inv, O[i][1] * inv,
                                O[i][2] * inv, O[i][3] * inv);
        *(float4*)(Ob + (size_t)(ty * 4 + i) * HH + tx * 4) = v4;
    }
}

// ---------------------------------------------------------------------------
// Row LayerNorm over H=768, one block (256 threads) per row.
// ---------------------------------------------------------------------------
__global__ void __launch_bounds__(256) layernorm_kernel(
    const float* __restrict__ y, const float* __restrict__ g,
    const float* __restrict__ be, float* __restrict__ out)
{
    __shared__ float red[256];
    int row = blockIdx.x;
    const float* yr = y + (size_t)row * HH;
    int t = threadIdx.x;
    float x0 = yr[t], x1 = yr[t + 256], x2 = yr[t + 512];
    red[t] = x0 + x1 + x2;
    __syncthreads();
    for (int s = 128; s > 0; s >>= 1) {
        if (t < s) red[t] += red[t + s];
        __syncthreads();
    }
    float mu = red[0] * (1.0f / HH);
    __syncthreads();
    float d0 = x0 - mu, d1 = x1 - mu, d2 = x2 - mu;
    red[t] = d0 * d0 + d1 * d1 + d2 * d2;
    __syncthreads();
    for (int s = 128; s > 0; s >>= 1) {
        if (t < s) red[t] += red[t + s];
        __syncthreads();
    }
    float rstd = rsqrtf(red[0] * (1.0f / HH) + 1e-12f);
    float* o = out + (size_t)row * HH;
    o[t]       = d0 * rstd * g[t]       + be[t];
    o[t + 256] = d1 * rstd * g[t + 256] + be[t + 256];
    o[t + 512] = d2 * rstd * g[t + 512] + be[t + 512];
}

// ---------------------------------------------------------------------------
extern "C" void kernel_launch(void* const* d_in, const int* in_sizes, int n_in,
                              void* d_out, int out_size)
{
    const float* hs   = (const float*)d_in[0];
    const float* mask = (const float*)d_in[1];
    const float* wq = (const float*)d_in[2];  const float* bq = (const float*)d_in[3];
    const float* wk = (const float*)d_in[4];  const float* bk = (const float*)d_in[5];
    const float* wv = (const float*)d_in[6];  const float* bv = (const float*)d_in[7];
    const float* afw = (const float*)d_in[8]; const float* afb = (const float*)d_in[9];
    const float* asw = (const float*)d_in[10];const float* asb = (const float*)d_in[11];
    const float* wi = (const float*)d_in[12]; const float* bi = (const float*)d_in[13];
    const float* wo = (const float*)d_in[14]; const float* bo = (const float*)d_in[15];
    const float* lg = (const float*)d_in[16]; const float* lb = (const float*)d_in[17];
    float* out = (float*)d_out;

    float *q, *k, *v, *attn, *adpt, *attn2, *inter, *y;
    cudaGetSymbolAddress((void**)&q,     g_q);
    cudaGetSymbolAddress((void**)&k,     g_k);
    cudaGetSymbolAddress((void**)&v,     g_v);
    cudaGetSymbolAddress((void**)&attn,  g_attn);
    cudaGetSymbolAddress((void**)&adpt,  g_adpt);
    cudaGetSymbolAddress((void**)&attn2, g_attn2);
    cudaGetSymbolAddress((void**)&inter, g_inter);
    cudaGetSymbolAddress((void**)&y,     g_y);

    dim3 blk(256);
    dim3 gH(HH / 128, MM / 128);     // N=768 GEMMs
    dim3 gFi(1, MM / 128);           // N=64 adapter down-proj
    dim3 gWi(FFF / 128, MM / 128);   // N=3072 FFN up-proj
    dim3 gA(SS / BQ, BB * NHH);      // attention

    // QKV projections
    sgemm_nt<0><<<gH, blk>>>(MM, HH, HH, hs, wq, bq, nullptr, q);
    sgemm_nt<0><<<gH, blk>>>(MM, HH, HH, hs, wk, bk, nullptr, k);
    sgemm_nt<0><<<gH, blk>>>(MM, HH, HH, hs, wv, bv, nullptr, v);
    // attention
    flash_attn_kernel<<<gA, blk>>>(q, k, v, mask, attn);
    // adapter bottleneck
    sgemm_nt<1><<<gFi, blk>>>(MM, ADD, HH, attn, afw, afb, nullptr, adpt);
    sgemm_nt<2><<<gH,  blk>>>(MM, HH, ADD, adpt, asw, asb, attn, attn2);
    // FFN
    sgemm_nt<1><<<gWi, blk>>>(MM, FFF, HH, attn2, wi, bi, nullptr, inter);
    sgemm_nt<2><<<gH,  blk>>>(MM, HH, FFF, inter, wo, bo, attn2, y);
    // LayerNorm -> output
    layernorm_kernel<<<MM, blk>>>(y, lg, lb, out);
}

// round 3
// speedup vs baseline: 2.1162x; 2.1162x over previous
#include <cuda_runtime.h>
#include <math.h>
#include <stdint.h>

#define BB   2
#define SS   2048
#define HH   768
#define NHH  12
#define DHH  64
#define FFF  3072
#define ADD  64
#define MM   (BB*SS)   // 4096

// ---------------- scratch (static device globals; no allocation) ----------
__device__ float g_q[MM*HH];
__device__ float g_k[MM*HH];
__device__ float g_v[MM*HH];
__device__ float g_attn[MM*HH];
__device__ float g_adpt[MM*ADD];
__device__ float g_attn2[MM*HH];
__device__ float g_inter[MM*FFF];
__device__ float g_y[MM*HH];

__device__ __forceinline__ float gelu_exact(float x) {
    return 0.5f * x * (1.0f + erff(x * 0.70710678118654752f));
}

__device__ __forceinline__ uint32_t f2tf32(float x) {
    uint32_t r;
    asm("cvt.rna.tf32.f32 %0, %1;" : "=r"(r) : "f"(x));
    return r;
}

// D += A*B  (m16n8k8 tf32)
__device__ __forceinline__ void mma8(float* d, const uint32_t* a,
                                     uint32_t b0, uint32_t b1) {
    asm volatile(
        "mma.sync.aligned.m16n8k8.row.col.f32.tf32.tf32.f32 "
        "{%0,%1,%2,%3}, {%4,%5,%6,%7}, {%8,%9}, {%0,%1,%2,%3};\n"
        : "+f"(d[0]), "+f"(d[1]), "+f"(d[2]), "+f"(d[3])
        : "r"(a[0]), "r"(a[1]), "r"(a[2]), "r"(a[3]), "r"(b0), "r"(b1));
}

// fast 2^x on the FMA pipe (no MUFU). x clamped at -126. |err| ~ 4e-5.
__device__ __forceinline__ float fexp2f(float x) {
    x = fmaxf(x, -126.0f);
    float t  = x + 12582912.0f;            // round-to-nearest-int
    float ri = t - 12582912.0f;
    float f  = x - ri;                     // f in [-0.5, 0.5]
    int   e  = __float_as_int(t) - 0x4B400000;
    float p  = fmaf(0.0096181291f, f, 0.0555041087f);
    p = fmaf(p, f, 0.2402265069f);
    p = fmaf(p, f, 0.69314718056f);
    p = fmaf(p, f, 1.0f);
    return __int_as_float((e + 127) << 23) * p;
}

// ---------------------------------------------------------------------------
// C[M,N] = A[M,K]*B[N,K]^T + bias (+epilogue), tf32 tensor cores.
// 128x128 block, BK=16, double-buffered smem, 256 threads = 8 warps (4m x 2n),
// warp tile 32x64. EPI: 0 bias, 1 bias+gelu, 2 bias+residual.
// Requires M%128==0, K%16==0.
// ---------------------------------------------------------------------------
#define GST 20   // smem row stride (words): conflict-free fragment loads

template<int EPI>
__global__ void __launch_bounds__(256) tgemm_nt(
    int M, int N, int K,
    const float* __restrict__ A, const float* __restrict__ B,
    const float* __restrict__ bias, const float* __restrict__ res,
    float* __restrict__ C)
{
    __shared__ uint32_t As[2][128][GST];
    __shared__ uint32_t Bs[2][128][GST];

    int t    = threadIdx.x;
    int lane = t & 31;
    int w    = t >> 5;
    int wm   = (w & 3) * 32;     // warp m offset
    int wn   = (w >> 2) * 64;    // warp n offset
    int rowBase = blockIdx.y * 128;
    int colBase = blockIdx.x * 128;

    int lr  = t >> 1;            // 0..127 smem row
    int lk8 = (t & 1) * 8;       // 0 or 8

    const float* Ap = A + (size_t)(rowBase + lr) * K + lk8;
    int brow = colBase + lr;
    bool bok = (brow < N);
    const float* Bp = B + (size_t)brow * K + lk8;

    float acc[2][8][4];
    #pragma unroll
    for (int i = 0; i < 2; i++)
        #pragma unroll
        for (int j = 0; j < 8; j++)
            #pragma unroll
            for (int l = 0; l < 4; l++) acc[i][j][l] = 0.f;

    float4 pa0, pa1, pb0, pb1;
    // prologue: tile 0 -> regs
    pa0 = *(const float4*)(Ap);
    pa1 = *(const float4*)(Ap + 4);
    pb0 = make_float4(0,0,0,0); pb1 = make_float4(0,0,0,0);
    if (bok) { pb0 = *(const float4*)(Bp); pb1 = *(const float4*)(Bp + 4); }

    int nk = K / 16;
    #pragma unroll 1
    for (int it = 0; it < nk; ++it) {
        int buf = it & 1;
        // store current regs -> smem[buf]
        {
            uint4 ua = make_uint4(f2tf32(pa0.x), f2tf32(pa0.y), f2tf32(pa0.z), f2tf32(pa0.w));
            uint4 ub = make_uint4(f2tf32(pa1.x), f2tf32(pa1.y), f2tf32(pa1.z), f2tf32(pa1.w));
            *(uint4*)&As[buf][lr][lk8]     = ua;
            *(uint4*)&As[buf][lr][lk8 + 4] = ub;
            uint4 va = make_uint4(f2tf32(pb0.x), f2tf32(pb0.y), f2tf32(pb0.z), f2tf32(pb0.w));
            uint4 vb = make_uint4(f2tf32(pb1.x), f2tf32(pb1.y), f2tf32(pb1.z), f2tf32(pb1.w));
            *(uint4*)&Bs[buf][lr][lk8]     = va;
            *(uint4*)&Bs[buf][lr][lk8 + 4] = vb;
        }
        __syncthreads();
        // prefetch next tile -> regs
        if (it + 1 < nk) {
            int k0 = (it + 1) * 16;
            pa0 = *(const float4*)(Ap + k0);
            pa1 = *(const float4*)(Ap + k0 + 4);
            if (bok) { pb0 = *(const float4*)(Bp + k0); pb1 = *(const float4*)(Bp + k0 + 4); }
        }
        // compute on smem[buf]
        #pragma unroll
        for (int ks = 0; ks < 2; ks++) {
            int kk = ks * 8;
            uint32_t af[2][4];
            #pragma unroll
            for (int mt = 0; mt < 2; mt++) {
                int r0 = wm + mt * 16 + (lane >> 2);
                af[mt][0] = As[buf][r0][kk + (lane & 3)];
                af[mt][1] = As[buf][r0 + 8][kk + (lane & 3)];
                af[mt][2] = As[buf][r0][kk + 4 + (lane & 3)];
                af[mt][3] = As[buf][r0 + 8][kk + 4 + (lane & 3)];
            }
            #pragma unroll
            for (int nt = 0; nt < 8; nt++) {
                int bn = wn + nt * 8 + (lane >> 2);
                uint32_t b0 = Bs[buf][bn][kk + (lane & 3)];
                uint32_t b1 = Bs[buf][bn][kk + 4 + (lane & 3)];
                mma8(acc[0][nt], af[0], b0, b1);
                mma8(acc[1][nt], af[1], b0, b1);
            }
        }
        __syncthreads();
    }

    // epilogue
    #pragma unroll
    for (int mt = 0; mt < 2; mt++) {
        int r0 = rowBase + wm + mt * 16 + (lane >> 2);
        #pragma unroll
        for (int nt = 0; nt < 8; nt++) {
            int c = colBase + wn + nt * 8 + 2 * (lane & 3);
            if (c < N) {
                float bsv0 = bias[c], bsv1 = bias[c + 1];
                float v0 = acc[mt][nt][0] + bsv0;
                float v1 = acc[mt][nt][1] + bsv1;
                float v2 = acc[mt][nt][2] + bsv0;
                float v3 = acc[mt][nt][3] + bsv1;
                if (EPI == 1) {
                    v0 = gelu_exact(v0); v1 = gelu_exact(v1);
                    v2 = gelu_exact(v2); v3 = gelu_exact(v3);
                }
                if (EPI == 2) {
                    const float* rp0 = res + (size_t)r0 * N + c;
                    const float* rp1 = res + (size_t)(r0 + 8) * N + c;
                    v0 += rp0[0]; v1 += rp0[1];
                    v2 += rp1[0]; v3 += rp1[1];
                }
                *(float2*)(C + (size_t)r0 * N + c)       = make_float2(v0, v1);
                *(float2*)(C + (size_t)(r0 + 8) * N + c) = make_float2(v2, v3);
            }
        }
    }
}

// ---------------------------------------------------------------------------
// Flash attention with tf32 tensor cores.
// BQ=64 rows/block, BKT=32 keys/iter, D=64. 128 threads = 4 warps, each warp
// owns 16 query rows. Q fragments live in registers for the whole kernel.
// Softmax exp via FMA-pipe poly (exp2 domain; scale folded into Q).
// ---------------------------------------------------------------------------
#define BQ   64
#define BKT  32
#define KST  68   // Ks/Qs row stride (words)
#define VST  36   // Vt/Ps row stride (words)

__global__ void __launch_bounds__(128) flash_attn_tc(
    const float* __restrict__ Q, const float* __restrict__ K,
    const float* __restrict__ V, const float* __restrict__ mask,
    float* __restrict__ out)
{
    __shared__ uint32_t Ks[BKT][KST];          // keys x d
    __shared__ uint32_t VtPs[2 * 64 * VST];    // Vt[64][VST] then Ps[64][VST]; aliased with Qs[64][KST]
    __shared__ float msk[BKT];

    #define QS(r, c) VtPs[(r) * KST + (c)]
    #define VT(d, k) VtPs[(d) * VST + (k)]
    #define PS(r, c) VtPs[64 * VST + (r) * VST + (c)]

    int t    = threadIdx.x;
    int lane = t & 31;
    int w    = t >> 5;
    int wm   = w * 16;
    int bh   = blockIdx.y;
    int b    = bh / NHH, h = bh % NHH;
    int q0   = blockIdx.x * BQ;

    const float qscale = 0.125f * 1.44269504088896f;  // 1/sqrt(64) * log2(e)

    const float* Qb = Q + ((size_t)(b * SS + q0)) * HH + h * DHH;
    const float* Kb = K + ((size_t)(b * SS)) * HH + h * DHH;
    const float* Vb = V + ((size_t)(b * SS)) * HH + h * DHH;
    const float* Mb = mask + (size_t)b * SS;

    // load Q tile (pre-scaled, tf32) into smem
    for (int i = t; i < BQ * 16; i += 128) {
        int r = i >> 4, c4 = (i & 15) * 4;
        float4 v4 = *(const float4*)(Qb + (size_t)r * HH + c4);
        uint4 u = make_uint4(f2tf32(v4.x * qscale), f2tf32(v4.y * qscale),
                             f2tf32(v4.z * qscale), f2tf32(v4.w * qscale));
        *(uint4*)&QS(r, c4) = u;
    }
    __syncthreads();

    // Q fragments -> registers (8 k-steps x 4 regs)
    uint32_t qf[8][4];
    {
        int r0 = wm + (lane >> 2);
        #pragma unroll
        for (int kt = 0; kt < 8; kt++) {
            int kk = kt * 8;
            qf[kt][0] = QS(r0,     kk + (lane & 3));
            qf[kt][1] = QS(r0 + 8, kk + (lane & 3));
            qf[kt][2] = QS(r0,     kk + 4 + (lane & 3));
            qf[kt][3] = QS(r0 + 8, kk + 4 + (lane & 3));
        }
    }
    __syncthreads();   // Qs region free for Vt/Ps reuse

    float o[8][4];
    #pragma unroll
    for (int i = 0; i < 8; i++)
        #pragma unroll
        for (int j = 0; j < 4; j++) o[i][j] = 0.f;
    float m0 = -1e30f, m1 = -1e30f, l0 = 0.f, l1 = 0.f;

    #pragma unroll 1
    for (int kb = 0; kb < SS; kb += BKT) {
        // --- load K (row-major) and V (transposed) tiles, tf32 ---
        for (int i = t; i < BKT * 16; i += 128) {
            int r = i >> 4, c4 = (i & 15) * 4;
            float4 kv = *(const float4*)(Kb + (size_t)(kb + r) * HH + c4);
            uint4 u = make_uint4(f2tf32(kv.x), f2tf32(kv.y), f2tf32(kv.z), f2tf32(kv.w));
            *(uint4*)&Ks[r][c4] = u;
        }
        for (int i = t; i < BKT * 16; i += 128) {
            int r = i & 31;            // key (distinct per lane -> conflict-free STS)
            int c4 = (i >> 5) * 4;     // d
            float4 vv = *(const float4*)(Vb + (size_t)(kb + r) * HH + c4);
            VT(c4 + 0, r) = f2tf32(vv.x);
            VT(c4 + 1, r) = f2tf32(vv.y);
            VT(c4 + 2, r) = f2tf32(vv.z);
            VT(c4 + 3, r) = f2tf32(vv.w);
        }
        if (t < BKT) msk[t] = Mb[kb + t] * 1.44269504088896f;
        __syncthreads();

        // --- S = Q K^T (4 key-tiles of 8) ---
        float s[4][4];
        #pragma unroll
        for (int nt = 0; nt < 4; nt++)
            #pragma unroll
            for (int j = 0; j < 4; j++) s[nt][j] = 0.f;
        #pragma unroll
        for (int kt = 0; kt < 8; kt++) {
            int kk = kt * 8;
            #pragma unroll
            for (int nt = 0; nt < 4; nt++) {
                int kr = nt * 8 + (lane >> 2);
                uint32_t b0 = Ks[kr][kk + (lane & 3)];
                uint32_t b1 = Ks[kr][kk + 4 + (lane & 3)];
                mma8(s[nt], qf[kt], b0, b1);
            }
        }

        // --- online softmax (exp2 domain, FMA-pipe exp) ---
        float mv[4][2];
        #pragma unroll
        for (int nt = 0; nt < 4; nt++) {
            int c = nt * 8 + 2 * (lane & 3);
            mv[nt][0] = msk[c]; mv[nt][1] = msk[c + 1];
        }
        float rmax0 = -1e30f, rmax1 = -1e30f;
        #pragma unroll
        for (int nt = 0; nt < 4; nt++) {
            s[nt][0] += mv[nt][0]; s[nt][1] += mv[nt][1];
            s[nt][2] += mv[nt][0]; s[nt][3] += mv[nt][1];
            rmax0 = fmaxf(rmax0, fmaxf(s[nt][0], s[nt][1]));
            rmax1 = fmaxf(rmax1, fmaxf(s[nt][2], s[nt][3]));
        }
        rmax0 = fmaxf(rmax0, __shfl_xor_sync(0xffffffffu, rmax0, 1));
        rmax0 = fmaxf(rmax0, __shfl_xor_sync(0xffffffffu, rmax0, 2));
        rmax1 = fmaxf(rmax1, __shfl_xor_sync(0xffffffffu, rmax1, 1));
        rmax1 = fmaxf(rmax1, __shfl_xor_sync(0xffffffffu, rmax1, 2));

        float nm0 = fmaxf(m0, rmax0), nm1 = fmaxf(m1, rmax1);
        float a0 = fexp2f(m0 - nm0), a1 = fexp2f(m1 - nm1);
        m0 = nm0; m1 = nm1;

        float sum0 = 0.f, sum1 = 0.f;
        int r0 = wm + (lane >> 2);
        #pragma unroll
        for (int nt = 0; nt < 4; nt++) {
            float p0 = fexp2f(s[nt][0] - nm0);
            float p1 = fexp2f(s[nt][1] - nm0);
            float p2 = fexp2f(s[nt][2] - nm1);
            float p3 = fexp2f(s[nt][3] - nm1);
            sum0 += p0 + p1; sum1 += p2 + p3;
            int c = nt * 8 + 2 * (lane & 3);
            *(uint2*)&PS(r0, c)     = make_uint2(f2tf32(p0), f2tf32(p1));
            *(uint2*)&PS(r0 + 8, c) = make_uint2(f2tf32(p2), f2tf32(p3));
        }
        sum0 += __shfl_xor_sync(0xffffffffu, sum0, 1);
        sum0 += __shfl_xor_sync(0xffffffffu, sum0, 2);
        sum1 += __shfl_xor_sync(0xffffffffu, sum1, 1);
        sum1 += __shfl_xor_sync(0xffffffffu, sum1, 2);
        l0 = l0 * a0 + sum0;
        l1 = l1 * a1 + sum1;

        #pragma unroll
        for (int dt = 0; dt < 8; dt++) {
            o[dt][0] *= a0; o[dt][1] *= a0;
            o[dt][2] *= a1; o[dt][3] *= a1;
        }
        __syncwarp();   // P visible within warp

        // --- O += P V ---
        #pragma unroll
        for (int kt = 0; kt < 4; kt++) {
            int kk = kt * 8;
            uint32_t af[4];
            af[0] = PS(r0,     kk + (lane & 3));
            af[1] = PS(r0 + 8, kk + (lane & 3));
            af[2] = PS(r0,     kk + 4 + (lane & 3));
            af[3] = PS(r0 + 8, kk + 4 + (lane & 3));
            #pragma unroll
            for (int dt = 0; dt < 8; dt++) {
                int vr = dt * 8 + (lane >> 2);
                uint32_t b0 = VT(vr, kk + (lane & 3));
                uint32_t b1 = VT(vr, kk + 4 + (lane & 3));
                mma8(o[dt], af, b0, b1);
            }
        }
        __syncthreads();
    }

    // --- write out ---
    float inv0 = 1.0f / l0, inv1 = 1.0f / l1;
    size_t gr = (size_t)(b * SS + q0 + wm + (lane >> 2));
    #pragma unroll
    for (int dt = 0; dt < 8; dt++) {
        int c = h * DHH + dt * 8 + 2 * (lane & 3);
        *(float2*)(out + gr * HH + c)       = make_float2(o[dt][0] * inv0, o[dt][1] * inv0);
        *(float2*)(out + (gr + 8) * HH + c) = make_float2(o[dt][2] * inv1, o[dt][3] * inv1);
    }
    #undef QS
    #undef VT
    #undef PS
}

// ---------------------------------------------------------------------------
// Row LayerNorm over H=768, one block (256 threads) per row.
// ---------------------------------------------------------------------------
__global__ void __launch_bounds__(256) layernorm_kernel(
    const float* __restrict__ y, const float* __restrict__ g,
    const float* __restrict__ be, float* __restrict__ out)
{
    __shared__ float red[256];
    int row = blockIdx.x;
    const float* yr = y + (size_t)row * HH;
    int t = threadIdx.x;
    float x0 = yr[t], x1 = yr[t + 256], x2 = yr[t + 512];
    red[t] = x0 + x1 + x2;
    __syncthreads();
    for (int s = 128; s > 0; s >>= 1) {
        if (t < s) red[t] += red[t + s];
        __syncthreads();
    }
    float mu = red[0] * (1.0f / HH);
    __syncthreads();
    float d0 = x0 - mu, d1 = x1 - mu, d2 = x2 - mu;
    red[t] = d0 * d0 + d1 * d1 + d2 * d2;
    __syncthreads();
    for (int s = 128; s > 0; s >>= 1) {
        if (t < s) red[t] += red[t + s];
        __syncthreads();
    }
    float rstd = rsqrtf(red[0] * (1.0f / HH) + 1e-12f);
    float* o = out + (size_t)row * HH;
    o[t]       = d0 * rstd * g[t]       + be[t];
    o[t + 256] = d1 * rstd * g[t + 256] + be[t + 256];
    o[t + 512] = d2 * rstd * g[t + 512] + be[t + 512];
}

// ---------------------------------------------------------------------------
extern "C" void kernel_launch(void* const* d_in, const int* in_sizes, int n_in,
                              void* d_out, int out_size)
{
    const float* hs   = (const float*)d_in[0];
    const float* mask = (const float*)d_in[1];
    const float* wq = (const float*)d_in[2];  const float* bq = (const float*)d_in[3];
    const float* wk = (const float*)d_in[4];  const float* bk = (const float*)d_in[5];
    const float* wv = (const float*)d_in[6];  const float* bv = (const float*)d_in[7];
    const float* afw = (const float*)d_in[8]; const float* afb = (const float*)d_in[9];
    const float* asw = (const float*)d_in[10];const float* asb = (const float*)d_in[11];
    const float* wi = (const float*)d_in[12]; const float* bi = (const float*)d_in[13];
    const float* wo = (const float*)d_in[14]; const float* bo = (const float*)d_in[15];
    const float* lg = (const float*)d_in[16]; const float* lb = (const float*)d_in[17];
    float* out = (float*)d_out;

    float *q, *k, *v, *attn, *adpt, *attn2, *inter, *y;
    cudaGetSymbolAddress((void**)&q,     g_q);
    cudaGetSymbolAddress((void**)&k,     g_k);
    cudaGetSymbolAddress((void**)&v,     g_v);
    cudaGetSymbolAddress((void**)&attn,  g_attn);
    cudaGetSymbolAddress((void**)&adpt,  g_adpt);
    cudaGetSymbolAddress((void**)&attn2, g_attn2);
    cudaGetSymbolAddress((void**)&inter, g_inter);
    cudaGetSymbolAddress((void**)&y,     g_y);

    dim3 blk(256);
    dim3 gH(HH / 128, MM / 128);     // N=768 GEMMs
    dim3 gFi(1, MM / 128);           // N=64 adapter down-proj
    dim3 gWi(FFF / 128, MM / 128);   // N=3072 FFN up-proj
    dim3 gA(SS / BQ, BB * NHH);      // attention

    // QKV projections
    tgemm_nt<0><<<gH, blk>>>(MM, HH, HH, hs, wq, bq, nullptr, q);
    tgemm_nt<0><<<gH, blk>>>(MM, HH, HH, hs, wk, bk, nullptr, k);
    tgemm_nt<0><<<gH, blk>>>(MM, HH, HH, hs, wv, bv, nullptr, v);
    // attention
    flash_attn_tc<<<gA, 128>>>(q, k, v, mask, attn);
    // adapter bottleneck
    tgemm_nt<1><<<gFi, blk>>>(MM, ADD, HH, attn, afw, afb, nullptr, adpt);
    tgemm_nt<2><<<gH,  blk>>>(MM, HH, ADD, adpt, asw, asb, attn, attn2);
    // FFN
    tgemm_nt<1><<<gWi, blk>>>(MM, FFF, HH, attn2, wi, bi, nullptr, inter);
    tgemm_nt<2><<<gH,  blk>>>(MM, HH, FFF, inter, wo, bo, attn2, y);
    // LayerNorm -> output
    layernorm_kernel<<<MM, blk>>>(y, lg, lb, out);
}

// round 4
// speedup vs baseline: 2.7834x; 1.3153x over previous
#include <cuda_runtime.h>
#include <math.h>
#include <stdint.h>

#define BB   2
#define SS   2048
#define HH   768
#define NHH  12
#define DHH  64
#define FFF  3072
#define ADD  64
#define MM   (BB*SS)   // 4096

#define LOG2E 1.44269504088896f

// ---------------- scratch (static device globals; no allocation) ----------
__device__ float g_q[MM*HH];
__device__ float g_k[MM*HH];
__device__ float g_v[MM*HH];
__device__ float g_attn[MM*HH];
__device__ float g_adpt[MM*ADD];
__device__ float g_attn2[MM*HH];
__device__ float g_inter[MM*FFF];
__device__ float g_y[MM*HH];

__device__ __forceinline__ float gelu_exact(float x) {
    return 0.5f * x * (1.0f + erff(x * 0.70710678118654752f));
}

__device__ __forceinline__ uint32_t f2tf32(float x) {
    uint32_t r;
    asm("cvt.rna.tf32.f32 %0, %1;" : "=r"(r) : "f"(x));
    return r;
}

// D += A*B  (m16n8k8 tf32)
__device__ __forceinline__ void mma8(float* d, const uint32_t* a,
                                     uint32_t b0, uint32_t b1) {
    asm volatile(
        "mma.sync.aligned.m16n8k8.row.col.f32.tf32.tf32.f32 "
        "{%0,%1,%2,%3}, {%4,%5,%6,%7}, {%8,%9}, {%0,%1,%2,%3};\n"
        : "+f"(d[0]), "+f"(d[1]), "+f"(d[2]), "+f"(d[3])
        : "r"(a[0]), "r"(a[1]), "r"(a[2]), "r"(a[3]), "r"(b0), "r"(b1));
}

// fast 2^x on the FMA pipe (no MUFU). x clamped at -126. |err| ~ 4e-5.
__device__ __forceinline__ float fexp2f(float x) {
    x = fmaxf(x, -126.0f);
    float t  = x + 12582912.0f;            // round-to-nearest-int
    float ri = t - 12582912.0f;
    float f  = x - ri;                     // f in [-0.5, 0.5]
    int   e  = __float_as_int(t) - 0x4B400000;
    float p  = fmaf(0.0096181291f, f, 0.0555041087f);
    p = fmaf(p, f, 0.2402265069f);
    p = fmaf(p, f, 0.69314718056f);
    p = fmaf(p, f, 1.0f);
    return __int_as_float((e + 127) << 23) * p;
}

// cp.async helpers
__device__ __forceinline__ void cpa16(uint32_t smem_addr, const void* gptr) {
    asm volatile("cp.async.cg.shared.global [%0], [%1], 16;"
                 :: "r"(smem_addr), "l"(gptr));
}
__device__ __forceinline__ void cpa_commit() {
    asm volatile("cp.async.commit_group;" ::: "memory");
}
__device__ __forceinline__ void cpa_wait0() {
    asm volatile("cp.async.wait_group 0;" ::: "memory");
}
__device__ __forceinline__ void cpa_wait1() {
    asm volatile("cp.async.wait_group 1;" ::: "memory");
}

// ---------------------------------------------------------------------------
// Generic C[M,N] = A[M,K]*B[N,K]^T + bias (+epilogue), tf32 tensor cores.
// 128x128 block, BK=16, double-buffered smem, 256 threads = 8 warps (4m x 2n),
// warp tile 32x64. EPI: 0 bias, 1 bias+gelu, 2 bias+residual.
// Requires M%128==0, K%16==0.
// ---------------------------------------------------------------------------
#define GST 20   // smem row stride (words): conflict-free fragment loads

template<int EPI>
__global__ void __launch_bounds__(256) tgemm_nt(
    int M, int N, int K,
    const float* __restrict__ A, const float* __restrict__ B,
    const float* __restrict__ bias, const float* __restrict__ res,
    float* __restrict__ C)
{
    __shared__ uint32_t As[2][128][GST];
    __shared__ uint32_t Bs[2][128][GST];

    int t    = threadIdx.x;
    int lane = t & 31;
    int w    = t >> 5;
    int wm   = (w & 3) * 32;
    int wn   = (w >> 2) * 64;
    int rowBase = blockIdx.y * 128;
    int colBase = blockIdx.x * 128;

    int lr  = t >> 1;
    int lk8 = (t & 1) * 8;

    const float* Ap = A + (size_t)(rowBase + lr) * K + lk8;
    int brow = colBase + lr;
    bool bok = (brow < N);
    const float* Bp = B + (size_t)brow * K + lk8;

    float acc[2][8][4];
    #pragma unroll
    for (int i = 0; i < 2; i++)
        #pragma unroll
        for (int j = 0; j < 8; j++)
            #pragma unroll
            for (int l = 0; l < 4; l++) acc[i][j][l] = 0.f;

    float4 pa0, pa1, pb0, pb1;
    pa0 = *(const float4*)(Ap);
    pa1 = *(const float4*)(Ap + 4);
    pb0 = make_float4(0,0,0,0); pb1 = make_float4(0,0,0,0);
    if (bok) { pb0 = *(const float4*)(Bp); pb1 = *(const float4*)(Bp + 4); }

    int nk = K / 16;
    #pragma unroll 1
    for (int it = 0; it < nk; ++it) {
        int buf = it & 1;
        {
            uint4 ua = make_uint4(f2tf32(pa0.x), f2tf32(pa0.y), f2tf32(pa0.z), f2tf32(pa0.w));
            uint4 ub = make_uint4(f2tf32(pa1.x), f2tf32(pa1.y), f2tf32(pa1.z), f2tf32(pa1.w));
            *(uint4*)&As[buf][lr][lk8]     = ua;
            *(uint4*)&As[buf][lr][lk8 + 4] = ub;
            uint4 va = make_uint4(f2tf32(pb0.x), f2tf32(pb0.y), f2tf32(pb0.z), f2tf32(pb0.w));
            uint4 vb = make_uint4(f2tf32(pb1.x), f2tf32(pb1.y), f2tf32(pb1.z), f2tf32(pb1.w));
            *(uint4*)&Bs[buf][lr][lk8]     = va;
            *(uint4*)&Bs[buf][lr][lk8 + 4] = vb;
        }
        __syncthreads();
        if (it + 1 < nk) {
            int k0 = (it + 1) * 16;
            pa0 = *(const float4*)(Ap + k0);
            pa1 = *(const float4*)(Ap + k0 + 4);
            if (bok) { pb0 = *(const float4*)(Bp + k0); pb1 = *(const float4*)(Bp + k0 + 4); }
        }
        #pragma unroll
        for (int ks = 0; ks < 2; ks++) {
            int kk = ks * 8;
            uint32_t af[2][4];
            #pragma unroll
            for (int mt = 0; mt < 2; mt++) {
                int r0 = wm + mt * 16 + (lane >> 2);
                af[mt][0] = As[buf][r0][kk + (lane & 3)];
                af[mt][1] = As[buf][r0 + 8][kk + (lane & 3)];
                af[mt][2] = As[buf][r0][kk + 4 + (lane & 3)];
                af[mt][3] = As[buf][r0 + 8][kk + 4 + (lane & 3)];
            }
            #pragma unroll
            for (int nt = 0; nt < 8; nt++) {
                int bn = wn + nt * 8 + (lane >> 2);
                uint32_t b0 = Bs[buf][bn][kk + (lane & 3)];
                uint32_t b1 = Bs[buf][bn][kk + 4 + (lane & 3)];
                mma8(acc[0][nt], af[0], b0, b1);
                mma8(acc[1][nt], af[1], b0, b1);
            }
        }
        __syncthreads();
    }

    #pragma unroll
    for (int mt = 0; mt < 2; mt++) {
        int r0 = rowBase + wm + mt * 16 + (lane >> 2);
        #pragma unroll
        for (int nt = 0; nt < 8; nt++) {
            int c = colBase + wn + nt * 8 + 2 * (lane & 3);
            if (c < N) {
                float bsv0 = bias[c], bsv1 = bias[c + 1];
                float v0 = acc[mt][nt][0] + bsv0;
                float v1 = acc[mt][nt][1] + bsv1;
                float v2 = acc[mt][nt][2] + bsv0;
                float v3 = acc[mt][nt][3] + bsv1;
                if (EPI == 1) {
                    v0 = gelu_exact(v0); v1 = gelu_exact(v1);
                    v2 = gelu_exact(v2); v3 = gelu_exact(v3);
                }
                if (EPI == 2) {
                    const float* rp0 = res + (size_t)r0 * N + c;
                    const float* rp1 = res + (size_t)(r0 + 8) * N + c;
                    v0 += rp0[0]; v1 += rp0[1];
                    v2 += rp1[0]; v3 += rp1[1];
                }
                *(float2*)(C + (size_t)r0 * N + c)       = make_float2(v0, v1);
                *(float2*)(C + (size_t)(r0 + 8) * N + c) = make_float2(v2, v3);
            }
        }
    }
}

// ---------------------------------------------------------------------------
// Fused QKV projection: one launch, gridDim.x = 18 (6 col-blocks x 3 outputs).
// Outputs are rounded to tf32 (rna); Q is additionally pre-scaled by
// 1/sqrt(DH)*log2(e) so flash attention consumes raw bits with no cvt.
// ---------------------------------------------------------------------------
__global__ void __launch_bounds__(256) tgemm_qkv(
    const float* __restrict__ A,
    const float* __restrict__ Bq, const float* __restrict__ Bk, const float* __restrict__ Bv,
    const float* __restrict__ bq, const float* __restrict__ bk, const float* __restrict__ bv,
    float* __restrict__ Cq, float* __restrict__ Ck, float* __restrict__ Cv)
{
    __shared__ uint32_t As[2][128][GST];
    __shared__ uint32_t Bs[2][128][GST];

    const int N = HH, K = HH;
    int which = blockIdx.x / 6;
    const float* B    = (which == 0) ? Bq : (which == 1) ? Bk : Bv;
    const float* bias = (which == 0) ? bq : (which == 1) ? bk : bv;
    float* C          = (which == 0) ? Cq : (which == 1) ? Ck : Cv;
    float scale = (which == 0) ? (0.125f * LOG2E) : 1.0f;

    int t    = threadIdx.x;
    int lane = t & 31;
    int w    = t >> 5;
    int wm   = (w & 3) * 32;
    int wn   = (w >> 2) * 64;
    int rowBase = blockIdx.y * 128;
    int colBase = (blockIdx.x % 6) * 128;

    int lr  = t >> 1;
    int lk8 = (t & 1) * 8;

    const float* Ap = A + (size_t)(rowBase + lr) * K + lk8;
    const float* Bp = B + (size_t)(colBase + lr) * K + lk8;

    float acc[2][8][4];
    #pragma unroll
    for (int i = 0; i < 2; i++)
        #pragma unroll
        for (int j = 0; j < 8; j++)
            #pragma unroll
            for (int l = 0; l < 4; l++) acc[i][j][l] = 0.f;

    float4 pa0 = *(const float4*)(Ap);
    float4 pa1 = *(const float4*)(Ap + 4);
    float4 pb0 = *(const float4*)(Bp);
    float4 pb1 = *(const float4*)(Bp + 4);

    int nk = K / 16;
    #pragma unroll 1
    for (int it = 0; it < nk; ++it) {
        int buf = it & 1;
        {
            uint4 ua = make_uint4(f2tf32(pa0.x), f2tf32(pa0.y), f2tf32(pa0.z), f2tf32(pa0.w));
            uint4 ub = make_uint4(f2tf32(pa1.x), f2tf32(pa1.y), f2tf32(pa1.z), f2tf32(pa1.w));
            *(uint4*)&As[buf][lr][lk8]     = ua;
            *(uint4*)&As[buf][lr][lk8 + 4] = ub;
            uint4 va = make_uint4(f2tf32(pb0.x), f2tf32(pb0.y), f2tf32(pb0.z), f2tf32(pb0.w));
            uint4 vb = make_uint4(f2tf32(pb1.x), f2tf32(pb1.y), f2tf32(pb1.z), f2tf32(pb1.w));
            *(uint4*)&Bs[buf][lr][lk8]     = va;
            *(uint4*)&Bs[buf][lr][lk8 + 4] = vb;
        }
        __syncthreads();
        if (it + 1 < nk) {
            int k0 = (it + 1) * 16;
            pa0 = *(const float4*)(Ap + k0);
            pa1 = *(const float4*)(Ap + k0 + 4);
            pb0 = *(const float4*)(Bp + k0);
            pb1 = *(const float4*)(Bp + k0 + 4);
        }
        #pragma unroll
        for (int ks = 0; ks < 2; ks++) {
            int kk = ks * 8;
            uint32_t af[2][4];
            #pragma unroll
            for (int mt = 0; mt < 2; mt++) {
                int r0 = wm + mt * 16 + (lane >> 2);
                af[mt][0] = As[buf][r0][kk + (lane & 3)];
                af[mt][1] = As[buf][r0 + 8][kk + (lane & 3)];
                af[mt][2] = As[buf][r0][kk + 4 + (lane & 3)];
                af[mt][3] = As[buf][r0 + 8][kk + 4 + (lane & 3)];
            }
            #pragma unroll
            for (int nt = 0; nt < 8; nt++) {
                int bn = wn + nt * 8 + (lane >> 2);
                uint32_t b0 = Bs[buf][bn][kk + (lane & 3)];
                uint32_t b1 = Bs[buf][bn][kk + 4 + (lane & 3)];
                mma8(acc[0][nt], af[0], b0, b1);
                mma8(acc[1][nt], af[1], b0, b1);
            }
        }
        __syncthreads();
    }

    #pragma unroll
    for (int mt = 0; mt < 2; mt++) {
        int r0 = rowBase + wm + mt * 16 + (lane >> 2);
        #pragma unroll
        for (int nt = 0; nt < 8; nt++) {
            int c = colBase + wn + nt * 8 + 2 * (lane & 3);
            float bsv0 = bias[c], bsv1 = bias[c + 1];
            float v0 = (acc[mt][nt][0] + bsv0) * scale;
            float v1 = (acc[mt][nt][1] + bsv1) * scale;
            float v2 = (acc[mt][nt][2] + bsv0) * scale;
            float v3 = (acc[mt][nt][3] + bsv1) * scale;
            uint2 u0 = make_uint2(f2tf32(v0), f2tf32(v1));
            uint2 u1 = make_uint2(f2tf32(v2), f2tf32(v3));
            *(uint2*)(C + (size_t)r0 * N + c)       = u0;
            *(uint2*)(C + (size_t)(r0 + 8) * N + c) = u1;
        }
    }
}

// ---------------------------------------------------------------------------
// Flash attention, tf32 tensor cores + cp.async double-buffered K/V pipeline.
// Q/K/V arrive tf32-pre-rounded (Q pre-scaled) from the QKV GEMM.
// BQ=64 rows/block, BKT=32 keys/iter, 4 warps; Q fragments via direct LDG.
// ---------------------------------------------------------------------------
#define BQ   64
#define BKT  32
#define KSW  68   // K smem row stride (words): S-frag reads conflict-free
#define VSW  72   // V smem row stride (words): PV B-frag reads conflict-free
#define PSW  36   // P smem row stride (words)

__global__ void __launch_bounds__(128, 5) flash_attn_tc(
    const float* __restrict__ Q, const float* __restrict__ K,
    const float* __restrict__ V, const float* __restrict__ mask,
    float* __restrict__ out)
{
    __shared__ __align__(16) uint32_t Ks[2][BKT][KSW];
    __shared__ __align__(16) uint32_t Vs[2][BKT][VSW];
    __shared__ __align__(16) uint32_t Ps[BQ][PSW];

    int t    = threadIdx.x;
    int lane = t & 31;
    int w    = t >> 5;
    int wm   = w * 16;
    int bh   = blockIdx.y;
    int b    = bh / NHH, h = bh % NHH;
    int q0   = blockIdx.x * BQ;

    const float* Kb = K + ((size_t)(b * SS)) * HH + h * DHH;
    const float* Vb = V + ((size_t)(b * SS)) * HH + h * DHH;
    const float* Mb = mask + (size_t)b * SS;

    // ---- Q fragments straight from global (already tf32 + scaled) ----
    uint32_t qf[8][4];
    {
        const float* Qb0 = Q + (size_t)(b * SS + q0 + wm + (lane >> 2)) * HH + h * DHH;
        const float* Qb1 = Qb0 + 8 * HH;
        #pragma unroll
        for (int kt = 0; kt < 8; kt++) {
            int c = kt * 8 + (lane & 3);
            qf[kt][0] = __float_as_uint(Qb0[c]);
            qf[kt][1] = __float_as_uint(Qb1[c]);
            qf[kt][2] = __float_as_uint(Qb0[c + 4]);
            qf[kt][3] = __float_as_uint(Qb1[c + 4]);
        }
    }

    // ---- prologue: issue K/V tile 0 ----
    {
        #pragma unroll
        for (int i = 0; i < 4; i++) {
            int id = t + i * 128;
            int r = id >> 4, c4 = (id & 15) * 4;
            cpa16((uint32_t)__cvta_generic_to_shared(&Ks[0][r][c4]),
                  Kb + (size_t)r * HH + c4);
            cpa16((uint32_t)__cvta_generic_to_shared(&Vs[0][r][c4]),
                  Vb + (size_t)r * HH + c4);
        }
        cpa_commit();
    }

    float o[8][4];
    #pragma unroll
    for (int i = 0; i < 8; i++)
        #pragma unroll
        for (int j = 0; j < 4; j++) o[i][j] = 0.f;
    float m0 = -1e30f, m1 = -1e30f, l0 = 0.f, l1 = 0.f;

    const int NIT = SS / BKT;
    #pragma unroll 1
    for (int it = 0; it < NIT; ++it) {
        int kb  = it * BKT;
        int buf = it & 1;

        // issue next tile into other buffer
        if (it + 1 < NIT) {
            int nb = buf ^ 1;
            const float* Kn = Kb + (size_t)(kb + BKT) * HH;
            const float* Vn = Vb + (size_t)(kb + BKT) * HH;
            #pragma unroll
            for (int i = 0; i < 4; i++) {
                int id = t + i * 128;
                int r = id >> 4, c4 = (id & 15) * 4;
                cpa16((uint32_t)__cvta_generic_to_shared(&Ks[nb][r][c4]),
                      Kn + (size_t)r * HH + c4);
                cpa16((uint32_t)__cvta_generic_to_shared(&Vs[nb][r][c4]),
                      Vn + (size_t)r * HH + c4);
            }
            cpa_commit();
            cpa_wait1();
        } else {
            cpa_wait0();
        }
        __syncthreads();

        // --- S = Q K^T ---
        float s[4][4];
        #pragma unroll
        for (int nt = 0; nt < 4; nt++)
            #pragma unroll
            for (int j = 0; j < 4; j++) s[nt][j] = 0.f;
        #pragma unroll
        for (int kt = 0; kt < 8; kt++) {
            int kk = kt * 8;
            #pragma unroll
            for (int nt = 0; nt < 4; nt++) {
                int kr = nt * 8 + (lane >> 2);
                uint32_t b0 = Ks[buf][kr][kk + (lane & 3)];
                uint32_t b1 = Ks[buf][kr][kk + 4 + (lane & 3)];
                mma8(s[nt], qf[kt], b0, b1);
            }
        }

        // --- online softmax (exp2 domain) ---
        float rmax0 = -1e30f, rmax1 = -1e30f;
        #pragma unroll
        for (int nt = 0; nt < 4; nt++) {
            int c = nt * 8 + 2 * (lane & 3);
            float2 mm = *(const float2*)(Mb + kb + c);
            float mv0 = mm.x * LOG2E, mv1 = mm.y * LOG2E;
            s[nt][0] += mv0; s[nt][1] += mv1;
            s[nt][2] += mv0; s[nt][3] += mv1;
            rmax0 = fmaxf(rmax0, fmaxf(s[nt][0], s[nt][1]));
            rmax1 = fmaxf(rmax1, fmaxf(s[nt][2], s[nt][3]));
        }
        rmax0 = fmaxf(rmax0, __shfl_xor_sync(0xffffffffu, rmax0, 1));
        rmax0 = fmaxf(rmax0, __shfl_xor_sync(0xffffffffu, rmax0, 2));
        rmax1 = fmaxf(rmax1, __shfl_xor_sync(0xffffffffu, rmax1, 1));
        rmax1 = fmaxf(rmax1, __shfl_xor_sync(0xffffffffu, rmax1, 2));

        float nm0 = fmaxf(m0, rmax0), nm1 = fmaxf(m1, rmax1);
        float a0 = fexp2f(m0 - nm0), a1 = fexp2f(m1 - nm1);
        m0 = nm0; m1 = nm1;

        float sum0 = 0.f, sum1 = 0.f;
        int r0 = wm + (lane >> 2);
        #pragma unroll
        for (int nt = 0; nt < 4; nt++) {
            float p0 = fexp2f(s[nt][0] - nm0);
            float p1 = fexp2f(s[nt][1] - nm0);
            float p2 = fexp2f(s[nt][2] - nm1);
            float p3 = fexp2f(s[nt][3] - nm1);
            sum0 += p0 + p1; sum1 += p2 + p3;
            int c = nt * 8 + 2 * (lane & 3);
            *(uint2*)&Ps[r0][c]     = make_uint2(f2tf32(p0), f2tf32(p1));
            *(uint2*)&Ps[r0 + 8][c] = make_uint2(f2tf32(p2), f2tf32(p3));
        }
        sum0 += __shfl_xor_sync(0xffffffffu, sum0, 1);
        sum0 += __shfl_xor_sync(0xffffffffu, sum0, 2);
        sum1 += __shfl_xor_sync(0xffffffffu, sum1, 1);
        sum1 += __shfl_xor_sync(0xffffffffu, sum1, 2);
        l0 = l0 * a0 + sum0;
        l1 = l1 * a1 + sum1;

        #pragma unroll
        for (int dt = 0; dt < 8; dt++) {
            o[dt][0] *= a0; o[dt][1] *= a0;
            o[dt][2] *= a1; o[dt][3] *= a1;
        }
        __syncwarp();   // Ps rows are per-warp private: warp sync suffices

        // --- O += P V ---
        #pragma unroll
        for (int kt = 0; kt < 4; kt++) {
            int kk = kt * 8;
            uint32_t af[4];
            af[0] = Ps[r0][kk + (lane & 3)];
            af[1] = Ps[r0 + 8][kk + (lane & 3)];
            af[2] = Ps[r0][kk + 4 + (lane & 3)];
            af[3] = Ps[r0 + 8][kk + 4 + (lane & 3)];
            #pragma unroll
            for (int dt = 0; dt < 8; dt++) {
                int dn = dt * 8 + (lane >> 2);
                uint32_t b0 = Vs[buf][kk + (lane & 3)][dn];
                uint32_t b1 = Vs[buf][kk + 4 + (lane & 3)][dn];
                mma8(o[dt], af, b0, b1);
            }
        }
        __syncthreads();   // protect Ks/Vs[buf] before next-next issue
    }

    // --- write out ---
    float inv0 = 1.0f / l0, inv1 = 1.0f / l1;
    size_t gr = (size_t)(b * SS + q0 + wm + (lane >> 2));
    #pragma unroll
    for (int dt = 0; dt < 8; dt++) {
        int c = h * DHH + dt * 8 + 2 * (lane & 3);
        *(float2*)(out + gr * HH + c)       = make_float2(o[dt][0] * inv0, o[dt][1] * inv0);
        *(float2*)(out + (gr + 8) * HH + c) = make_float2(o[dt][2] * inv1, o[dt][3] * inv1);
    }
}

// ---------------------------------------------------------------------------
// Row LayerNorm over H=768, one block (256 threads) per row.
// ---------------------------------------------------------------------------
__global__ void __launch_bounds__(256) layernorm_kernel(
    const float* __restrict__ y, const float* __restrict__ g,
    const float* __restrict__ be, float* __restrict__ out)
{
    __shared__ float red[256];
    int row = blockIdx.x;
    const float* yr = y + (size_t)row * HH;
    int t = threadIdx.x;
    float x0 = yr[t], x1 = yr[t + 256], x2 = yr[t + 512];
    red[t] = x0 + x1 + x2;
    __syncthreads();
    for (int s = 128; s > 0; s >>= 1) {
        if (t < s) red[t] += red[t + s];
        __syncthreads();
    }
    float mu = red[0] * (1.0f / HH);
    __syncthreads();
    float d0 = x0 - mu, d1 = x1 - mu, d2 = x2 - mu;
    red[t] = d0 * d0 + d1 * d1 + d2 * d2;
    __syncthreads();
    for (int s = 128; s > 0; s >>= 1) {
        if (t < s) red[t] += red[t + s];
        __syncthreads();
    }
    float rstd = rsqrtf(red[0] * (1.0f / HH) + 1e-12f);
    float* o = out + (size_t)row * HH;
    o[t]       = d0 * rstd * g[t]       + be[t];
    o[t + 256] = d1 * rstd * g[t + 256] + be[t + 256];
    o[t + 512] = d2 * rstd * g[t + 512] + be[t + 512];
}

// ---------------------------------------------------------------------------
extern "C" void kernel_launch(void* const* d_in, const int* in_sizes, int n_in,
                              void* d_out, int out_size)
{
    const float* hs   = (const float*)d_in[0];
    const float* mask = (const float*)d_in[1];
    const float* wq = (const float*)d_in[2];  const float* bq = (const float*)d_in[3];
    const float* wk = (const float*)d_in[4];  const float* bk = (const float*)d_in[5];
    const float* wv = (const float*)d_in[6];  const float* bv = (const float*)d_in[7];
    const float* afw = (const float*)d_in[8]; const float* afb = (const float*)d_in[9];
    const float* asw = (const float*)d_in[10];const float* asb = (const float*)d_in[11];
    const float* wi = (const float*)d_in[12]; const float* bi = (const float*)d_in[13];
    const float* wo = (const float*)d_in[14]; const float* bo = (const float*)d_in[15];
    const float* lg = (const float*)d_in[16]; const float* lb = (const float*)d_in[17];
    float* out = (float*)d_out;

    float *q, *k, *v, *attn, *adpt, *attn2, *inter, *y;
    cudaGetSymbolAddress((void**)&q,     g_q);
    cudaGetSymbolAddress((void**)&k,     g_k);
    cudaGetSymbolAddress((void**)&v,     g_v);
    cudaGetSymbolAddress((void**)&attn,  g_attn);
    cudaGetSymbolAddress((void**)&adpt,  g_adpt);
    cudaGetSymbolAddress((void**)&attn2, g_attn2);
    cudaGetSymbolAddress((void**)&inter, g_inter);
    cudaGetSymbolAddress((void**)&y,     g_y);

    dim3 blk(256);
    dim3 gQKV(18, MM / 128);         // fused QKV
    dim3 gH(HH / 128, MM / 128);
    dim3 gFi(1, MM / 128);
    dim3 gWi(FFF / 128, MM / 128);
    dim3 gA(SS / BQ, BB * NHH);

    // fused QKV projection (outputs tf32-rounded; Q pre-scaled)
    tgemm_qkv<<<gQKV, blk>>>(hs, wq, wk, wv, bq, bk, bv, q, k, v);
    // attention
    flash_attn_tc<<<gA, 128>>>(q, k, v, mask, attn);
    // adapter bottleneck
    tgemm_nt<1><<<gFi, blk>>>(MM, ADD, HH, attn, afw, afb, nullptr, adpt);
    tgemm_nt<2><<<gH,  blk>>>(MM, HH, ADD, adpt, asw, asb, attn, attn2);
    // FFN
    tgemm_nt<1><<<gWi, blk>>>(MM, FFF, HH, attn2, wi, bi, nullptr, inter);
    tgemm_nt<2><<<gH,  blk>>>(MM, HH, FFF, inter, wo, bo, attn2, y);
    // LayerNorm -> output
    layernorm_kernel<<<MM, blk>>>(y, lg, lb, out);
}

// round 8
// speedup vs baseline: 3.0139x; 1.0828x over previous
#include <cuda_runtime.h>
#include <math.h>
#include <stdint.h>

#define BB   2
#define SS   2048
#define HH   768
#define NHH  12
#define DHH  64
#define FFF  3072
#define ADD  64
#define MM   (BB*SS)   // 4096

#define LOG2E 1.44269504088896f

// ---------------- scratch (static device globals; no allocation) ----------
__device__ float g_q[MM*HH];       // tf32-rounded, Q pre-scaled
__device__ float g_k[MM*HH];       // tf32-rounded
__device__ float g_v[MM*HH];       // tf32-rounded
__device__ float g_attn[MM*HH];    // raw fp32 (residual path)
__device__ float g_attnr[MM*HH];   // tf32-rounded (GEMM A path)
__device__ float g_adpt[MM*ADD];   // tf32-rounded
__device__ float g_attn2[MM*HH];   // raw fp32 (residual path)
__device__ float g_attn2r[MM*HH];  // tf32-rounded (GEMM A path)
__device__ float g_inter[MM*FFF];  // tf32-rounded
__device__ float g_y[MM*HH];       // raw fp32
// tf32-rounded operand copies
__device__ float g_hsr[MM*HH];
__device__ float g_wqr[HH*HH];
__device__ float g_wkr[HH*HH];
__device__ float g_wvr[HH*HH];
__device__ float g_afwr[ADD*HH];
__device__ float g_aswr[HH*ADD];
__device__ float g_wir[FFF*HH];
__device__ float g_wor[HH*FFF];

__device__ __forceinline__ float gelu_exact(float x) {
    return 0.5f * x * (1.0f + erff(x * 0.70710678118654752f));
}

__device__ __forceinline__ uint32_t f2tf32(float x) {
    uint32_t r;
    asm("cvt.rna.tf32.f32 %0, %1;" : "=r"(r) : "f"(x));
    return r;
}

// D += A*B  (m16n8k8 tf32)
__device__ __forceinline__ void mma8(float* d, const uint32_t* a,
                                     uint32_t b0, uint32_t b1) {
    asm volatile(
        "mma.sync.aligned.m16n8k8.row.col.f32.tf32.tf32.f32 "
        "{%0,%1,%2,%3}, {%4,%5,%6,%7}, {%8,%9}, {%0,%1,%2,%3};\n"
        : "+f"(d[0]), "+f"(d[1]), "+f"(d[2]), "+f"(d[3])
        : "r"(a[0]), "r"(a[1]), "r"(a[2]), "r"(a[3]), "r"(b0), "r"(b1));
}

// fast 2^x on the FMA pipe. x clamped at -126. |err| ~ 4e-5.
__device__ __forceinline__ float fexp2f(float x) {
    x = fmaxf(x, -126.0f);
    float t  = x + 12582912.0f;
    float ri = t - 12582912.0f;
    float f  = x - ri;
    int   e  = __float_as_int(t) - 0x4B400000;
    float p  = fmaf(0.0096181291f, f, 0.0555041087f);
    p = fmaf(p, f, 0.2402265069f);
    p = fmaf(p, f, 0.69314718056f);
    p = fmaf(p, f, 1.0f);
    return __int_as_float((e + 127) << 23) * p;
}

// ---------------- cp.async helpers ----------------
__device__ __forceinline__ void cpa16(uint32_t smem_addr, const void* gptr) {
    asm volatile("cp.async.cg.shared.global [%0], [%1], 16;"
                 :: "r"(smem_addr), "l"(gptr));
}
__device__ __forceinline__ void cpa_commit() {
    asm volatile("cp.async.commit_group;" ::: "memory");
}
__device__ __forceinline__ void cpa_wait0() {
    asm volatile("cp.async.wait_group 0;" ::: "memory");
}
__device__ __forceinline__ void cpa_wait1() {
    asm volatile("cp.async.wait_group 1;" ::: "memory");
}
__device__ __forceinline__ void cpa_wait2() {
    asm volatile("cp.async.wait_group 2;" ::: "memory");
}
__device__ __forceinline__ uint32_t smem_u32(const void* p) {
    uint32_t a;
    asm("{ .reg .u64 t; cvta.to.shared.u64 t, %1; cvt.u32.u64 %0, t; }"
        : "=r"(a) : "l"(p));
    return a;
}

// ---------------------------------------------------------------------------
// GEMM: C[M,N] = A[M,K]*B[N,K]^T + bias (+epilogue), tf32 mma.sync.
// Operands MUST be pre-rounded to tf32 in memory (bits consumed raw).
// 128x128 tile, BK=16, 3-stage cp.async ring, 256 threads = 8 warps (4m x 2n),
// warp tile 32x64.
// EPI: 0 (bias)*scale, 1 bias+gelu, 2 bias+residual.
// STORE: 0 raw->C, 1 rounded->C, 2 raw->C + rounded->Cr.
// ---------------------------------------------------------------------------
#define GST   20
#define TILEW (128 * GST)              // words per A (or B) stage
#define GSM_BYTES (3 * 2 * TILEW * 4)  // 61440

template<int EPI, int STORE>
__device__ __forceinline__ void tgemm_core(
    int M, int N, int K,
    const float* __restrict__ A, const float* __restrict__ B,
    const float* __restrict__ bias, const float* __restrict__ res,
    float* __restrict__ C, float* __restrict__ Cr,
    int rowBase, int colBase, float scale)
{
    extern __shared__ __align__(16) uint32_t sm[];

    int t    = threadIdx.x;
    int lane = t & 31;
    int w    = t >> 5;
    int wm   = (w & 3) * 32;
    int wn   = (w >> 2) * 64;

    int lr  = t >> 1;            // 0..127
    int lk8 = (t & 1) * 8;       // 0 or 8

    const float* Ap = A + (size_t)(rowBase + lr) * K + lk8;
    int brow = colBase + lr;
    bool bok = (brow < N);
    const float* Bp = B + (size_t)brow * K + lk8;

    uint32_t aAddr[3], bAddr[3];
    #pragma unroll
    for (int s = 0; s < 3; s++) {
        aAddr[s] = smem_u32(sm + s * TILEW + lr * GST + lk8);
        bAddr[s] = smem_u32(sm + 3 * TILEW + s * TILEW + lr * GST + lk8);
    }

    float acc[2][8][4];
    #pragma unroll
    for (int i = 0; i < 2; i++)
        #pragma unroll
        for (int j = 0; j < 8; j++)
            #pragma unroll
            for (int l = 0; l < 4; l++) acc[i][j][l] = 0.f;

    int nk = K / 16;
    // prologue: issue tiles 0..2
    #pragma unroll
    for (int s = 0; s < 3; s++) {
        if (s < nk) {
            int k0 = s * 16;
            cpa16(aAddr[s],      Ap + k0);
            cpa16(aAddr[s] + 16, Ap + k0 + 4);
            if (bok) {
                cpa16(bAddr[s],      Bp + k0);
                cpa16(bAddr[s] + 16, Bp + k0 + 4);
            }
        }
        cpa_commit();
    }

    #pragma unroll 1
    for (int it = 0; it < nk; ++it) {
        int buf = it % 3;
        cpa_wait2();
        __syncthreads();

        const uint32_t* Asb = sm + buf * TILEW;
        const uint32_t* Bsb = sm + 3 * TILEW + buf * TILEW;

        #pragma unroll
        for (int ks = 0; ks < 2; ks++) {
            int kk = ks * 8;
            uint32_t af[2][4];
            #pragma unroll
            for (int mt = 0; mt < 2; mt++) {
                int r0 = wm + mt * 16 + (lane >> 2);
                af[mt][0] = Asb[r0 * GST + kk + (lane & 3)];
                af[mt][1] = Asb[(r0 + 8) * GST + kk + (lane & 3)];
                af[mt][2] = Asb[r0 * GST + kk + 4 + (lane & 3)];
                af[mt][3] = Asb[(r0 + 8) * GST + kk + 4 + (lane & 3)];
            }
            #pragma unroll
            for (int nt = 0; nt < 8; nt++) {
                int bn = wn + nt * 8 + (lane >> 2);
                uint32_t b0 = Bsb[bn * GST + kk + (lane & 3)];
                uint32_t b1 = Bsb[bn * GST + kk + 4 + (lane & 3)];
                mma8(acc[0][nt], af[0], b0, b1);
                mma8(acc[1][nt], af[1], b0, b1);
            }
        }
        __syncthreads();

        if (it + 3 < nk) {
            int k0 = (it + 3) * 16;
            cpa16(aAddr[buf],      Ap + k0);
            cpa16(aAddr[buf] + 16, Ap + k0 + 4);
            if (bok) {
                cpa16(bAddr[buf],      Bp + k0);
                cpa16(bAddr[buf] + 16, Bp + k0 + 4);
            }
        }
        cpa_commit();
    }

    // epilogue
    #pragma unroll
    for (int mt = 0; mt < 2; mt++) {
        int r0 = rowBase + wm + mt * 16 + (lane >> 2);
        #pragma unroll
        for (int nt = 0; nt < 8; nt++) {
            int c = colBase + wn + nt * 8 + 2 * (lane & 3);
            if (c < N) {
                float bsv0 = bias[c], bsv1 = bias[c + 1];
                float v0 = acc[mt][nt][0] + bsv0;
                float v1 = acc[mt][nt][1] + bsv1;
                float v2 = acc[mt][nt][2] + bsv0;
                float v3 = acc[mt][nt][3] + bsv1;
                if (EPI == 0) { v0 *= scale; v1 *= scale; v2 *= scale; v3 *= scale; }
                if (EPI == 1) {
                    v0 = gelu_exact(v0); v1 = gelu_exact(v1);
                    v2 = gelu_exact(v2); v3 = gelu_exact(v3);
                }
                if (EPI == 2) {
                    const float* rp0 = res + (size_t)r0 * N + c;
                    const float* rp1 = res + (size_t)(r0 + 8) * N + c;
                    v0 += rp0[0]; v1 += rp0[1];
                    v2 += rp1[0]; v3 += rp1[1];
                }
                if (STORE == 0 || STORE == 2) {
                    *(float2*)(C + (size_t)r0 * N + c)       = make_float2(v0, v1);
                    *(float2*)(C + (size_t)(r0 + 8) * N + c) = make_float2(v2, v3);
                }
                if (STORE == 1) {
                    *(uint2*)(C + (size_t)r0 * N + c) =
                        make_uint2(f2tf32(v0), f2tf32(v1));
                    *(uint2*)(C + (size_t)(r0 + 8) * N + c) =
                        make_uint2(f2tf32(v2), f2tf32(v3));
                }
                if (STORE == 2) {
                    *(uint2*)(Cr + (size_t)r0 * N + c) =
                        make_uint2(f2tf32(v0), f2tf32(v1));
                    *(uint2*)(Cr + (size_t)(r0 + 8) * N + c) =
                        make_uint2(f2tf32(v2), f2tf32(v3));
                }
            }
        }
    }
}

template<int EPI, int STORE>
__global__ void __launch_bounds__(256) tgemm_cp(
    int M, int N, int K,
    const float* __restrict__ A, const float* __restrict__ B,
    const float* __restrict__ bias, const float* __restrict__ res,
    float* __restrict__ C, float* __restrict__ Cr)
{
    tgemm_core<EPI, STORE>(M, N, K, A, B, bias, res, C, Cr,
                           blockIdx.y * 128, blockIdx.x * 128, 1.0f);
}

// fused QKV: gridDim.x = 18 (6 col-tiles x 3 outputs); outputs rounded,
// Q additionally pre-scaled by 1/sqrt(DH)*log2(e).
__global__ void __launch_bounds__(256) tgemm_qkv(
    const float* __restrict__ A,
    const float* __restrict__ Bq, const float* __restrict__ Bk, const float* __restrict__ Bv,
    const float* __restrict__ bq, const float* __restrict__ bk, const float* __restrict__ bv,
    float* __restrict__ Cq, float* __restrict__ Ck, float* __restrict__ Cv)
{
    int which = blockIdx.x / 6;
    const float* B    = (which == 0) ? Bq : (which == 1) ? Bk : Bv;
    const float* bias = (which == 0) ? bq : (which == 1) ? bk : bv;
    float* C          = (which == 0) ? Cq : (which == 1) ? Ck : Cv;
    float scale       = (which == 0) ? (0.125f * LOG2E) : 1.0f;
    tgemm_core<0, 1>(MM, HH, HH, A, B, bias, nullptr, C, nullptr,
                     blockIdx.y * 128, (blockIdx.x % 6) * 128, scale);
}

// ---------------------------------------------------------------------------
// Pre-round hs + weights to tf32 (rna) — feeds all GEMMs.
// ---------------------------------------------------------------------------
#define P0 786432u
#define P1 933888u
#define P2 1081344u
#define P3 1228800u
#define P4 1241088u
#define P5 1253376u
#define P6 1843200u
#define P7 2433024u
__global__ void __launch_bounds__(256) round_prep(
    const float4* hs, const float4* wq, const float4* wk, const float4* wv,
    const float4* afw, const float4* asw, const float4* wi, const float4* wo,
    float4* ohs, float4* owq, float4* owk, float4* owv,
    float4* oafw, float4* oasw, float4* owi, float4* owo)
{
    for (uint32_t i = blockIdx.x * 256u + threadIdx.x; i < P7;
         i += gridDim.x * 256u) {
        const float4* src; float4* dst; uint32_t j;
        if      (i < P0) { src = hs;  dst = ohs;  j = i; }
        else if (i < P1) { src = wq;  dst = owq;  j = i - P0; }
        else if (i < P2) { src = wk;  dst = owk;  j = i - P1; }
        else if (i < P3) { src = wv;  dst = owv;  j = i - P2; }
        else if (i < P4) { src = afw; dst = oafw; j = i - P3; }
        else if (i < P5) { src = asw; dst = oasw; j = i - P4; }
        else if (i < P6) { src = wi;  dst = owi;  j = i - P5; }
        else             { src = wo;  dst = owo;  j = i - P6; }
        float4 v = src[j];
        uint4 u = make_uint4(f2tf32(v.x), f2tf32(v.y), f2tf32(v.z), f2tf32(v.w));
        *(uint4*)&dst[j] = u;
    }
}

// ---------------------------------------------------------------------------
// Flash attention, tf32 mma.sync + cp.async double-buffered K/V pipeline.
// Q/K/V arrive tf32-pre-rounded (Q pre-scaled). Writes raw + rounded outputs.
// ---------------------------------------------------------------------------
#define BQ   64
#define BKT  32
#define KSW  68
#define VSW  72
#define PSW  36

__global__ void __launch_bounds__(128, 5) flash_attn_tc(
    const float* __restrict__ Q, const float* __restrict__ K,
    const float* __restrict__ V, const float* __restrict__ mask,
    float* __restrict__ out, float* __restrict__ outr)
{
    __shared__ __align__(16) uint32_t Ks[2][BKT][KSW];
    __shared__ __align__(16) uint32_t Vs[2][BKT][VSW];
    __shared__ __align__(16) uint32_t Ps[BQ][PSW];

    int t    = threadIdx.x;
    int lane = t & 31;
    int w    = t >> 5;
    int wm   = w * 16;
    int bh   = blockIdx.y;
    int b    = bh / NHH, h = bh % NHH;
    int q0   = blockIdx.x * BQ;

    const float* Kb = K + ((size_t)(b * SS)) * HH + h * DHH;
    const float* Vb = V + ((size_t)(b * SS)) * HH + h * DHH;
    const float* Mb = mask + (size_t)b * SS;

    uint32_t qf[8][4];
    {
        const float* Qb0 = Q + (size_t)(b * SS + q0 + wm + (lane >> 2)) * HH + h * DHH;
        const float* Qb1 = Qb0 + 8 * HH;
        #pragma unroll
        for (int kt = 0; kt < 8; kt++) {
            int c = kt * 8 + (lane & 3);
            qf[kt][0] = __float_as_uint(Qb0[c]);
            qf[kt][1] = __float_as_uint(Qb1[c]);
            qf[kt][2] = __float_as_uint(Qb0[c + 4]);
            qf[kt][3] = __float_as_uint(Qb1[c + 4]);
        }
    }

    {
        #pragma unroll
        for (int i = 0; i < 4; i++) {
            int id = t + i * 128;
            int r = id >> 4, c4 = (id & 15) * 4;
            cpa16((uint32_t)__cvta_generic_to_shared(&Ks[0][r][c4]),
                  Kb + (size_t)r * HH + c4);
            cpa16((uint32_t)__cvta_generic_to_shared(&Vs[0][r][c4]),
                  Vb + (size_t)r * HH + c4);
        }
        cpa_commit();
    }

    float o[8][4];
    #pragma unroll
    for (int i = 0; i < 8; i++)
        #pragma unroll
        for (int j = 0; j < 4; j++) o[i][j] = 0.f;
    float m0 = -1e30f, m1 = -1e30f, l0 = 0.f, l1 = 0.f;

    const int NIT = SS / BKT;
    #pragma unroll 1
    for (int it = 0; it < NIT; ++it) {
        int kb  = it * BKT;
        int buf = it & 1;

        if (it + 1 < NIT) {
            int nb = buf ^ 1;
            const float* Kn = Kb + (size_t)(kb + BKT) * HH;
            const float* Vn = Vb + (size_t)(kb + BKT) * HH;
            #pragma unroll
            for (int i = 0; i < 4; i++) {
                int id = t + i * 128;
                int r = id >> 4, c4 = (id & 15) * 4;
                cpa16((uint32_t)__cvta_generic_to_shared(&Ks[nb][r][c4]),
                      Kn + (size_t)r * HH + c4);
                cpa16((uint32_t)__cvta_generic_to_shared(&Vs[nb][r][c4]),
                      Vn + (size_t)r * HH + c4);
            }
            cpa_commit();
            cpa_wait1();
        } else {
            cpa_wait0();
        }
        __syncthreads();

        float s[4][4];
        #pragma unroll
        for (int nt = 0; nt < 4; nt++)
            #pragma unroll
            for (int j = 0; j < 4; j++) s[nt][j] = 0.f;
        #pragma unroll
        for (int kt = 0; kt < 8; kt++) {
            int kk = kt * 8;
            #pragma unroll
            for (int nt = 0; nt < 4; nt++) {
                int kr = nt * 8 + (lane >> 2);
                uint32_t b0 = Ks[buf][kr][kk + (lane & 3)];
                uint32_t b1 = Ks[buf][kr][kk + 4 + (lane & 3)];
                mma8(s[nt], qf[kt], b0, b1);
            }
        }

        float rmax0 = -1e30f, rmax1 = -1e30f;
        #pragma unroll
        for (int nt = 0; nt < 4; nt++) {
            int c = nt * 8 + 2 * (lane & 3);
            float2 mm = *(const float2*)(Mb + kb + c);
            float mv0 = mm.x * LOG2E, mv1 = mm.y * LOG2E;
            s[nt][0] += mv0; s[nt][1] += mv1;
            s[nt][2] += mv0; s[nt][3] += mv1;
            rmax0 = fmaxf(rmax0, fmaxf(s[nt][0], s[nt][1]));
            rmax1 = fmaxf(rmax1, fmaxf(s[nt][2], s[nt][3]));
        }
        rmax0 = fmaxf(rmax0, __shfl_xor_sync(0xffffffffu, rmax0, 1));
        rmax0 = fmaxf(rmax0, __shfl_xor_sync(0xffffffffu, rmax0, 2));
        rmax1 = fmaxf(rmax1, __shfl_xor_sync(0xffffffffu, rmax1, 1));
        rmax1 = fmaxf(rmax1, __shfl_xor_sync(0xffffffffu, rmax1, 2));

        float nm0 = fmaxf(m0, rmax0), nm1 = fmaxf(m1, rmax1);
        float a0 = fexp2f(m0 - nm0), a1 = fexp2f(m1 - nm1);
        m0 = nm0; m1 = nm1;

        float sum0 = 0.f, sum1 = 0.f;
        int r0 = wm + (lane >> 2);
        #pragma unroll
        for (int nt = 0; nt < 4; nt++) {
            float p0 = fexp2f(s[nt][0] - nm0);
            float p1 = fexp2f(s[nt][1] - nm0);
            float p2 = fexp2f(s[nt][2] - nm1);
            float p3 = fexp2f(s[nt][3] - nm1);
            sum0 += p0 + p1; sum1 += p2 + p3;
            int c = nt * 8 + 2 * (lane & 3);
            *(uint2*)&Ps[r0][c]     = make_uint2(f2tf32(p0), f2tf32(p1));
            *(uint2*)&Ps[r0 + 8][c] = make_uint2(f2tf32(p2), f2tf32(p3));
        }
        sum0 += __shfl_xor_sync(0xffffffffu, sum0, 1);
        sum0 += __shfl_xor_sync(0xffffffffu, sum0, 2);
        sum1 += __shfl_xor_sync(0xffffffffu, sum1, 1);
        sum1 += __shfl_xor_sync(0xffffffffu, sum1, 2);
        l0 = l0 * a0 + sum0;
        l1 = l1 * a1 + sum1;

        #pragma unroll
        for (int dt = 0; dt < 8; dt++) {
            o[dt][0] *= a0; o[dt][1] *= a0;
            o[dt][2] *= a1; o[dt][3] *= a1;
        }
        __syncwarp();

        #pragma unroll
        for (int kt = 0; kt < 4; kt++) {
            int kk = kt * 8;
            uint32_t af[4];
            af[0] = Ps[r0][kk + (lane & 3)];
            af[1] = Ps[r0 + 8][kk + (lane & 3)];
            af[2] = Ps[r0][kk + 4 + (lane & 3)];
            af[3] = Ps[r0 + 8][kk + 4 + (lane & 3)];
            #pragma unroll
            for (int dt = 0; dt < 8; dt++) {
                int dn = dt * 8 + (lane >> 2);
                uint32_t b0 = Vs[buf][kk + (lane & 3)][dn];
                uint32_t b1 = Vs[buf][kk + 4 + (lane & 3)][dn];
                mma8(o[dt], af, b0, b1);
            }
        }
        __syncthreads();
    }

    // write out: raw (residual path) + tf32-rounded (GEMM A path)
    float inv0 = 1.0f / l0, inv1 = 1.0f / l1;
    size_t gr = (size_t)(b * SS + q0 + wm + (lane >> 2));
    #pragma unroll
    for (int dt = 0; dt < 8; dt++) {
        int c = h * DHH + dt * 8 + 2 * (lane & 3);
        float v0 = o[dt][0] * inv0, v1 = o[dt][1] * inv0;
        float v2 = o[dt][2] * inv1, v3 = o[dt][3] * inv1;
        *(float2*)(out + gr * HH + c)        = make_float2(v0, v1);
        *(float2*)(out + (gr + 8) * HH + c)  = make_float2(v2, v3);
        *(uint2*)(outr + gr * HH + c)        = make_uint2(f2tf32(v0), f2tf32(v1));
        *(uint2*)(outr + (gr + 8) * HH + c)  = make_uint2(f2tf32(v2), f2tf32(v3));
    }
}

// ---------------------------------------------------------------------------
// Row LayerNorm over H=768, one block (256 threads) per row.
// ---------------------------------------------------------------------------
__global__ void __launch_bounds__(256) layernorm_kernel(
    const float* __restrict__ y, const float* __restrict__ g,
    const float* __restrict__ be, float* __restrict__ out)
{
    __shared__ float red[256];
    int row = blockIdx.x;
    const float* yr = y + (size_t)row * HH;
    int t = threadIdx.x;
    float x0 = yr[t], x1 = yr[t + 256], x2 = yr[t + 512];
    red[t] = x0 + x1 + x2;
    __syncthreads();
    for (int s = 128; s > 0; s >>= 1) {
        if (t < s) red[t] += red[t + s];
        __syncthreads();
    }
    float mu = red[0] * (1.0f / HH);
    __syncthreads();
    float d0 = x0 - mu, d1 = x1 - mu, d2 = x2 - mu;
    red[t] = d0 * d0 + d1 * d1 + d2 * d2;
    __syncthreads();
    for (int s = 128; s > 0; s >>= 1) {
        if (t < s) red[t] += red[t + s];
        __syncthreads();
    }
    float rstd = rsqrtf(red[0] * (1.0f / HH) + 1e-12f);
    float* o = out + (size_t)row * HH;
    o[t]       = d0 * rstd * g[t]       + be[t];
    o[t + 256] = d1 * rstd * g[t + 256] + be[t + 256];
    o[t + 512] = d2 * rstd * g[t + 512] + be[t + 512];
}

// ---------------------------------------------------------------------------
extern "C" void kernel_launch(void* const* d_in, const int* in_sizes, int n_in,
                              void* d_out, int out_size)
{
    const float* hs   = (const float*)d_in[0];
    const float* mask = (const float*)d_in[1];
    const float* wq = (const float*)d_in[2];  const float* bq = (const float*)d_in[3];
    const float* wk = (const float*)d_in[4];  const float* bk = (const float*)d_in[5];
    const float* wv = (const float*)d_in[6];  const float* bv = (const float*)d_in[7];
    const float* afw = (const float*)d_in[8]; const float* afb = (const float*)d_in[9];
    const float* asw = (const float*)d_in[10];const float* asb = (const float*)d_in[11];
    const float* wi = (const float*)d_in[12]; const float* bi = (const float*)d_in[13];
    const float* wo = (const float*)d_in[14]; const float* bo = (const float*)d_in[15];
    const float* lg = (const float*)d_in[16]; const float* lb = (const float*)d_in[17];
    float* out = (float*)d_out;

    float *q, *k, *v, *attn, *attnr, *adpt, *attn2, *attn2r, *inter, *y;
    float *hsr, *wqr, *wkr, *wvr, *afwr, *aswr, *wir, *wor;
    cudaGetSymbolAddress((void**)&q,      g_q);
    cudaGetSymbolAddress((void**)&k,      g_k);
    cudaGetSymbolAddress((void**)&v,      g_v);
    cudaGetSymbolAddress((void**)&attn,   g_attn);
    cudaGetSymbolAddress((void**)&attnr,  g_attnr);
    cudaGetSymbolAddress((void**)&adpt,   g_adpt);
    cudaGetSymbolAddress((void**)&attn2,  g_attn2);
    cudaGetSymbolAddress((void**)&attn2r, g_attn2r);
    cudaGetSymbolAddress((void**)&inter,  g_inter);
    cudaGetSymbolAddress((void**)&y,      g_y);
    cudaGetSymbolAddress((void**)&hsr,    g_hsr);
    cudaGetSymbolAddress((void**)&wqr,    g_wqr);
    cudaGetSymbolAddress((void**)&wkr,    g_wkr);
    cudaGetSymbolAddress((void**)&wvr,    g_wvr);
    cudaGetSymbolAddress((void**)&afwr,   g_afwr);
    cudaGetSymbolAddress((void**)&aswr,   g_aswr);
    cudaGetSymbolAddress((void**)&wir,    g_wir);
    cudaGetSymbolAddress((void**)&wor,    g_wor);

    cudaFuncSetAttribute(tgemm_qkv,
        cudaFuncAttributeMaxDynamicSharedMemorySize, GSM_BYTES);
    cudaFuncSetAttribute(tgemm_cp<1, 1>,
        cudaFuncAttributeMaxDynamicSharedMemorySize, GSM_BYTES);
    cudaFuncSetAttribute(tgemm_cp<2, 2>,
        cudaFuncAttributeMaxDynamicSharedMemorySize, GSM_BYTES);
    cudaFuncSetAttribute(tgemm_cp<2, 0>,
        cudaFuncAttributeMaxDynamicSharedMemorySize, GSM_BYTES);

    // 0) round operands to tf32 (rna)
    round_prep<<<1024, 256>>>(
        (const float4*)hs, (const float4*)wq, (const float4*)wk, (const float4*)wv,
        (const float4*)afw, (const float4*)asw, (const float4*)wi, (const float4*)wo,
        (float4*)hsr, (float4*)wqr, (float4*)wkr, (float4*)wvr,
        (float4*)afwr, (float4*)aswr, (float4*)wir, (float4*)wor);

    // 1) fused QKV projection (outputs tf32-rounded; Q pre-scaled)
    tgemm_qkv<<<dim3(18, 32), 256, GSM_BYTES>>>(
        hsr, wqr, wkr, wvr, bq, bk, bv, q, k, v);

    // 2) attention (raw + rounded outputs)
    flash_attn_tc<<<dim3(SS / BQ, BB * NHH), 128>>>(q, k, v, mask, attn, attnr);

    // 3) adapter bottleneck
    tgemm_cp<1, 1><<<dim3(1, 32), 256, GSM_BYTES>>>(
        MM, ADD, HH, attnr, afwr, afb, nullptr, adpt, nullptr);
    tgemm_cp<2, 2><<<dim3(6, 32), 256, GSM_BYTES>>>(
        MM, HH, ADD, adpt, aswr, asb, attn, attn2, attn2r);

    // 4) FFN
    tgemm_cp<1, 1><<<dim3(24, 32), 256, GSM_BYTES>>>(
        MM, FFF, HH, attn2r, wir, bi, nullptr, inter, nullptr);
    tgemm_cp<2, 0><<<dim3(6, 32), 256, GSM_BYTES>>>(
        MM, HH, FFF, inter, wor, bo, attn2, y, nullptr);

    // 5) LayerNorm -> output
    layernorm_kernel<<<MM, 256>>>(y, lg, lb, out);
}

// round 9
// speedup vs baseline: 5.2709x; 1.7489x over previous
#include <cuda_runtime.h>
#include <cuda_fp16.h>
#include <math.h>
#include <stdint.h>

#define BB   2
#define SS   2048
#define HH   768
#define NHH  12
#define DHH  64
#define FFF  3072
#define ADD  64
#define MM   (BB*SS)   // 4096

#define LOG2E 1.44269504088896f

// ---------------- scratch (static device globals; no allocation) ----------
__device__ __half g_qh[MM*HH];      // fp16, Q pre-scaled by 0.125*log2(e)
__device__ __half g_kh[MM*HH];      // fp16
__device__ __half g_vth[MM*HH];     // fp16, layout [B][NH][DH][S]
__device__ float  g_attn[MM*HH];    // raw fp32 (residual path)
__device__ __half g_attnrh[MM*HH];  // fp16 (GEMM A path)
__device__ __half g_adpth[MM*ADD];  // fp16
__device__ float  g_attn2[MM*HH];   // raw fp32 (residual path)
__device__ __half g_attn2rh[MM*HH]; // fp16 (GEMM A path)
__device__ __half g_interh[MM*FFF]; // fp16
__device__ float  g_y[MM*HH];       // raw fp32
// fp16 operand copies of inputs
__device__ __half g_hsh[MM*HH];
__device__ __half g_wqh[HH*HH];
__device__ __half g_wkh[HH*HH];
__device__ __half g_wvh[HH*HH];
__device__ __half g_afwh[ADD*HH];
__device__ __half g_aswh[HH*ADD];
__device__ __half g_wih[FFF*HH];
__device__ __half g_woh[HH*FFF];

__device__ __forceinline__ float gelu_exact(float x) {
    return 0.5f * x * (1.0f + erff(x * 0.70710678118654752f));
}

// D += A*B  (m16n8k16 f16, fp32 accum)
__device__ __forceinline__ void mma16(float* d, const uint32_t* a,
                                      uint32_t b0, uint32_t b1) {
    asm volatile(
        "mma.sync.aligned.m16n8k16.row.col.f32.f16.f16.f32 "
        "{%0,%1,%2,%3}, {%4,%5,%6,%7}, {%8,%9}, {%0,%1,%2,%3};\n"
        : "+f"(d[0]), "+f"(d[1]), "+f"(d[2]), "+f"(d[3])
        : "r"(a[0]), "r"(a[1]), "r"(a[2]), "r"(a[3]), "r"(b0), "r"(b1));
}

// fast 2^x on the FMA pipe. x clamped at -126. |err| ~ 4e-5.
__device__ __forceinline__ float fexp2f(float x) {
    x = fmaxf(x, -126.0f);
    float t  = x + 12582912.0f;
    float ri = t - 12582912.0f;
    float f  = x - ri;
    int   e  = __float_as_int(t) - 0x4B400000;
    float p  = fmaf(0.0096181291f, f, 0.0555041087f);
    p = fmaf(p, f, 0.2402265069f);
    p = fmaf(p, f, 0.69314718056f);
    p = fmaf(p, f, 1.0f);
    return __int_as_float((e + 127) << 23) * p;
}

// ---------------- cp.async helpers ----------------
__device__ __forceinline__ void cpa16(uint32_t smem_addr, const void* gptr) {
    asm volatile("cp.async.cg.shared.global [%0], [%1], 16;"
                 :: "r"(smem_addr), "l"(gptr));
}
__device__ __forceinline__ void cpa_commit() {
    asm volatile("cp.async.commit_group;" ::: "memory");
}
__device__ __forceinline__ void cpa_wait0() {
    asm volatile("cp.async.wait_group 0;" ::: "memory");
}
__device__ __forceinline__ void cpa_wait1() {
    asm volatile("cp.async.wait_group 1;" ::: "memory");
}
__device__ __forceinline__ void cpa_wait2() {
    asm volatile("cp.async.wait_group 2;" ::: "memory");
}
__device__ __forceinline__ uint32_t smem_u32(const void* p) {
    uint32_t a;
    asm("{ .reg .u64 t; cvta.to.shared.u64 t, %1; cvt.u32.u64 %0, t; }"
        : "=r"(a) : "l"(p));
    return a;
}
__device__ __forceinline__ uint32_t h2u(__half2 h) {
    return *(uint32_t*)&h;
}

// ---------------------------------------------------------------------------
// GEMM: C = A[M,K]*B[N,K]^T + bias (+epilogue), fp16 mma m16n8k16, fp32 accum.
// 128x128 tile, BK=32 halfs, 3-stage cp.async ring, 256 thr = 8 warps (4m x 2n).
// EPI: 0 (bias)*scale, 1 bias+gelu, 2 bias+residual.
// STORE: 0 fp32->C; 1 fp16->Cr; 2 both. VTOUT: scatter fp16 to Vt[b][h][d][s].
// ---------------------------------------------------------------------------
#define GST   20                       // words per smem row (16 data + 4 pad)
#define TILEW (128 * GST)
#define GSM_BYTES (3 * 2 * TILEW * 4)  // 61440

template<int EPI, int STORE, bool VTOUT>
__device__ __forceinline__ void tgemm_core(
    int M, int N, int K,
    const __half* __restrict__ A, const __half* __restrict__ B,
    const float* __restrict__ bias, const float* __restrict__ res,
    float* __restrict__ C, __half* __restrict__ Cr, __half* __restrict__ Vt,
    int rowBase, int colBase, float scale)
{
    extern __shared__ __align__(16) uint32_t sm[];

    int t    = threadIdx.x;
    int lane = t & 31;
    int w    = t >> 5;
    int wm   = (w & 3) * 32;
    int wn   = (w >> 2) * 64;

    int lr   = t >> 1;            // 0..127
    int lh16 = (t & 1) * 16;      // half offset 0 or 16

    const __half* Ap = A + (size_t)(rowBase + lr) * K + lh16;
    int brow = colBase + lr;
    bool bok = (brow < N);
    const __half* Bp = B + (size_t)brow * K + lh16;

    uint32_t aAddr[3], bAddr[3];
    #pragma unroll
    for (int s = 0; s < 3; s++) {
        aAddr[s] = smem_u32(sm + s * TILEW + lr * GST + (t & 1) * 8);
        bAddr[s] = smem_u32(sm + 3 * TILEW + s * TILEW + lr * GST + (t & 1) * 8);
    }

    float acc[2][8][4];
    #pragma unroll
    for (int i = 0; i < 2; i++)
        #pragma unroll
        for (int j = 0; j < 8; j++)
            #pragma unroll
            for (int l = 0; l < 4; l++) acc[i][j][l] = 0.f;

    int nk = K / 32;
    // prologue: issue tiles 0..2
    #pragma unroll
    for (int s = 0; s < 3; s++) {
        if (s < nk) {
            int k0 = s * 32;
            cpa16(aAddr[s],      Ap + k0);
            cpa16(aAddr[s] + 16, Ap + k0 + 8);
            if (bok) {
                cpa16(bAddr[s],      Bp + k0);
                cpa16(bAddr[s] + 16, Bp + k0 + 8);
            }
        }
        cpa_commit();
    }

    #pragma unroll 1
    for (int it = 0; it < nk; ++it) {
        int buf = it % 3;
        cpa_wait2();
        __syncthreads();

        const uint32_t* Asb = sm + buf * TILEW;
        const uint32_t* Bsb = sm + 3 * TILEW + buf * TILEW;

        #pragma unroll
        for (int ks = 0; ks < 2; ks++) {
            int kk = ks * 8;
            uint32_t af[2][4];
            #pragma unroll
            for (int mt = 0; mt < 2; mt++) {
                int r0 = wm + mt * 16 + (lane >> 2);
                af[mt][0] = Asb[r0 * GST + kk + (lane & 3)];
                af[mt][1] = Asb[(r0 + 8) * GST + kk + (lane & 3)];
                af[mt][2] = Asb[r0 * GST + kk + 4 + (lane & 3)];
                af[mt][3] = Asb[(r0 + 8) * GST + kk + 4 + (lane & 3)];
            }
            #pragma unroll
            for (int nt = 0; nt < 8; nt++) {
                int bn = wn + nt * 8 + (lane >> 2);
                uint32_t b0 = Bsb[bn * GST + kk + (lane & 3)];
                uint32_t b1 = Bsb[bn * GST + kk + 4 + (lane & 3)];
                mma16(acc[0][nt], af[0], b0, b1);
                mma16(acc[1][nt], af[1], b0, b1);
            }
        }
        __syncthreads();

        if (it + 3 < nk) {
            int k0 = (it + 3) * 32;
            cpa16(aAddr[buf],      Ap + k0);
            cpa16(aAddr[buf] + 16, Ap + k0 + 8);
            if (bok) {
                cpa16(bAddr[buf],      Bp + k0);
                cpa16(bAddr[buf] + 16, Bp + k0 + 8);
            }
        }
        cpa_commit();
    }

    // epilogue
    #pragma unroll
    for (int mt = 0; mt < 2; mt++) {
        int r0 = rowBase + wm + mt * 16 + (lane >> 2);
        #pragma unroll
        for (int nt = 0; nt < 8; nt++) {
            int c = colBase + wn + nt * 8 + 2 * (lane & 3);
            if (c < N) {
                float bsv0 = bias[c], bsv1 = bias[c + 1];
                float v0 = acc[mt][nt][0] + bsv0;
                float v1 = acc[mt][nt][1] + bsv1;
                float v2 = acc[mt][nt][2] + bsv0;
                float v3 = acc[mt][nt][3] + bsv1;
                if (EPI == 0) { v0 *= scale; v1 *= scale; v2 *= scale; v3 *= scale; }
                if (EPI == 1) {
                    v0 = gelu_exact(v0); v1 = gelu_exact(v1);
                    v2 = gelu_exact(v2); v3 = gelu_exact(v3);
                }
                if (EPI == 2) {
                    const float* rp0 = res + (size_t)r0 * N + c;
                    const float* rp1 = res + (size_t)(r0 + 8) * N + c;
                    v0 += rp0[0]; v1 += rp0[1];
                    v2 += rp1[0]; v3 += rp1[1];
                }
                if (VTOUT) {
                    // scatter to Vt[b][h][d][s]
                    int hh = c >> 6, d = c & 63;
                    int b0i = r0 >> 11, s0 = r0 & 2047;
                    size_t base = (((size_t)b0i * NHH + hh) * DHH + d) * SS;
                    Vt[base + s0]          = __float2half_rn(v0);
                    Vt[base + SS + s0]     = __float2half_rn(v1);
                    Vt[base + s0 + 8]      = __float2half_rn(v2);
                    Vt[base + SS + s0 + 8] = __float2half_rn(v3);
                } else {
                    if (STORE == 0 || STORE == 2) {
                        *(float2*)(C + (size_t)r0 * N + c)       = make_float2(v0, v1);
                        *(float2*)(C + (size_t)(r0 + 8) * N + c) = make_float2(v2, v3);
                    }
                    if (STORE >= 1) {
                        *(__half2*)(Cr + (size_t)r0 * N + c) =
                            __floats2half2_rn(v0, v1);
                        *(__half2*)(Cr + (size_t)(r0 + 8) * N + c) =
                            __floats2half2_rn(v2, v3);
                    }
                }
            }
        }
    }
}

template<int EPI, int STORE>
__global__ void __launch_bounds__(256) tgemm_cp(
    int M, int N, int K,
    const __half* __restrict__ A, const __half* __restrict__ B,
    const float* __restrict__ bias, const float* __restrict__ res,
    float* __restrict__ C, __half* __restrict__ Cr)
{
    tgemm_core<EPI, STORE, false>(M, N, K, A, B, bias, res, C, Cr, nullptr,
                                  blockIdx.y * 128, blockIdx.x * 128, 1.0f);
}

// fused QKV: gridDim.x = 18 (6 col-tiles x 3 outputs).
// Q pre-scaled by 0.125*log2(e); V written transposed to Vt[b][h][d][s].
__global__ void __launch_bounds__(256) tgemm_qkv(
    const __half* __restrict__ A,
    const __half* __restrict__ Bq, const __half* __restrict__ Bk, const __half* __restrict__ Bv,
    const float* __restrict__ bq, const float* __restrict__ bk, const float* __restrict__ bv,
    __half* __restrict__ Cq, __half* __restrict__ Ck, __half* __restrict__ Vt)
{
    int which = blockIdx.x / 6;
    int rb = blockIdx.y * 128, cb = (blockIdx.x % 6) * 128;
    if (which == 0) {
        tgemm_core<0, 1, false>(MM, HH, HH, A, Bq, bq, nullptr, nullptr, Cq,
                                nullptr, rb, cb, 0.125f * LOG2E);
    } else if (which == 1) {
        tgemm_core<0, 1, false>(MM, HH, HH, A, Bk, bk, nullptr, nullptr, Ck,
                                nullptr, rb, cb, 1.0f);
    } else {
        tgemm_core<0, 1, true>(MM, HH, HH, A, Bv, bv, nullptr, nullptr, nullptr,
                               Vt, rb, cb, 1.0f);
    }
}

// ---------------------------------------------------------------------------
// Adapter down-proj: C[MM,64] = gelu(A[MM,768]*W[64,768]^T + b), fp16.
// 32-row tiles -> 128 blocks, 128 threads = 4 warps (2m x 2n), warp 16x32.
// ---------------------------------------------------------------------------
__global__ void __launch_bounds__(128) adapter_down(
    const __half* __restrict__ A, const __half* __restrict__ W,
    const float* __restrict__ bias, __half* __restrict__ C)
{
    __shared__ __align__(16) uint32_t As[3][32][GST];
    __shared__ __align__(16) uint32_t Bs[3][64][GST];

    int t    = threadIdx.x;
    int lane = t & 31;
    int w    = t >> 5;
    int wm   = (w & 1) * 16;
    int wn   = (w >> 1) * 32;
    int rowBase = blockIdx.x * 32;

    const __half* Ap = A + (size_t)(rowBase + (t >> 1)) * HH + (t & 1) * 16;
    const __half* Bp = W + (size_t)(t >> 1) * HH + (t & 1) * 16;
    uint32_t aAddr[3], bAddr[3];
    #pragma unroll
    for (int s = 0; s < 3; s++) {
        aAddr[s] = smem_u32(&As[s][t >> 2][0]) + ((t & 3) & 1) * 0; // placeholder
        aAddr[s] = smem_u32(&As[s][(t >> 1) & 31][(t & 1) * 8]);
        bAddr[s] = smem_u32(&Bs[s][t >> 1][(t & 1) * 8]);
    }
    bool aok = (t < 64);

    float acc[4][4];
    #pragma unroll
    for (int j = 0; j < 4; j++)
        #pragma unroll
        for (int l = 0; l < 4; l++) acc[j][l] = 0.f;

    const int nk = HH / 32;  // 24
    #pragma unroll
    for (int s = 0; s < 3; s++) {
        int k0 = s * 32;
        if (aok) {
            cpa16(aAddr[s],      Ap + k0);
            cpa16(aAddr[s] + 16, Ap + k0 + 8);
        }
        cpa16(bAddr[s],      Bp + k0);
        cpa16(bAddr[s] + 16, Bp + k0 + 8);
        cpa_commit();
    }

    #pragma unroll 1
    for (int it = 0; it < nk; ++it) {
        int buf = it % 3;
        cpa_wait2();
        __syncthreads();

        #pragma unroll
        for (int ks = 0; ks < 2; ks++) {
            int kk = ks * 8;
            int r0 = wm + (lane >> 2);
            uint32_t af[4];
            af[0] = As[buf][r0][kk + (lane & 3)];
            af[1] = As[buf][r0 + 8][kk + (lane & 3)];
            af[2] = As[buf][r0][kk + 4 + (lane & 3)];
            af[3] = As[buf][r0 + 8][kk + 4 + (lane & 3)];
            #pragma unroll
            for (int nt = 0; nt < 4; nt++) {
                int bn = wn + nt * 8 + (lane >> 2);
                uint32_t b0 = Bs[buf][bn][kk + (lane & 3)];
                uint32_t b1 = Bs[buf][bn][kk + 4 + (lane & 3)];
                mma16(acc[nt], af, b0, b1);
            }
        }
        __syncthreads();

        if (it + 3 < nk) {
            int k0 = (it + 3) * 32;
            if (aok) {
                cpa16(aAddr[buf],      Ap + k0);
                cpa16(aAddr[buf] + 16, Ap + k0 + 8);
            }
            cpa16(bAddr[buf],      Bp + k0);
            cpa16(bAddr[buf] + 16, Bp + k0 + 8);
        }
        cpa_commit();
    }

    int r0 = rowBase + wm + (lane >> 2);
    #pragma unroll
    for (int nt = 0; nt < 4; nt++) {
        int c = wn + nt * 8 + 2 * (lane & 3);
        float b0 = bias[c], b1 = bias[c + 1];
        float v0 = gelu_exact(acc[nt][0] + b0);
        float v1 = gelu_exact(acc[nt][1] + b1);
        float v2 = gelu_exact(acc[nt][2] + b0);
        float v3 = gelu_exact(acc[nt][3] + b1);
        *(__half2*)(C + (size_t)r0 * ADD + c)       = __floats2half2_rn(v0, v1);
        *(__half2*)(C + (size_t)(r0 + 8) * ADD + c) = __floats2half2_rn(v2, v3);
    }
}

// ---------------------------------------------------------------------------
// Pre-round hs + weights to fp16 — feeds all GEMMs.
// ---------------------------------------------------------------------------
#define P0 786432u
#define P1 933888u
#define P2 1081344u
#define P3 1228800u
#define P4 1241088u
#define P5 1253376u
#define P6 1843200u
#define P7 2433024u
__global__ void __launch_bounds__(256) round_prep(
    const float4* hs, const float4* wq, const float4* wk, const float4* wv,
    const float4* afw, const float4* asw, const float4* wi, const float4* wo,
    __half* ohs, __half* owq, __half* owk, __half* owv,
    __half* oafw, __half* oasw, __half* owi, __half* owo)
{
    for (uint32_t i = blockIdx.x * 256u + threadIdx.x; i < P7;
         i += gridDim.x * 256u) {
        const float4* src; __half* dst; uint32_t j;
        if      (i < P0) { src = hs;  dst = ohs;  j = i; }
        else if (i < P1) { src = wq;  dst = owq;  j = i - P0; }
        else if (i < P2) { src = wk;  dst = owk;  j = i - P1; }
        else if (i < P3) { src = wv;  dst = owv;  j = i - P2; }
        else if (i < P4) { src = afw; dst = oafw; j = i - P3; }
        else if (i < P5) { src = asw; dst = oasw; j = i - P4; }
        else if (i < P6) { src = wi;  dst = owi;  j = i - P5; }
        else             { src = wo;  dst = owo;  j = i - P6; }
        float4 v = src[j];
        uint2 u = make_uint2(h2u(__floats2half2_rn(v.x, v.y)),
                             h2u(__floats2half2_rn(v.z, v.w)));
        *(uint2*)(dst + 4 * j) = u;
    }
}

// ---------------------------------------------------------------------------
// Flash attention, fp16 mma m16n8k16 + cp.async double-buffered K/V pipeline.
// Q/K pre-scaled/rounded fp16 natural layout; V transposed [b][h][d][s].
// BQ=64, BKT=32, 4 warps.
// ---------------------------------------------------------------------------
#define KSW2  36   // K smem row stride (words), 32 data
#define VSW2  20   // Vt smem row stride (words), 16 data
#define PSW2  20   // P smem row stride (words), 16 data

__global__ void __launch_bounds__(128, 5) flash_attn_h(
    const __half* __restrict__ Q, const __half* __restrict__ K,
    const __half* __restrict__ Vt, const float* __restrict__ mask,
    float* __restrict__ out, __half* __restrict__ outr)
{
    __shared__ __align__(16) uint32_t Ks[2][32][KSW2];
    __shared__ __align__(16) uint32_t Vts[2][64][VSW2];
    __shared__ __align__(16) uint32_t Ps[64][PSW2];

    int t    = threadIdx.x;
    int lane = t & 31;
    int w    = t >> 5;
    int wm   = w * 16;
    int bh   = blockIdx.y;
    int b    = bh / NHH, h = bh % NHH;
    int q0   = blockIdx.x * 64;

    const __half* Kb = K + (size_t)(b * SS) * HH + h * DHH;
    const __half* Vb = Vt + ((size_t)(b * NHH + h) * DHH) * SS;
    const float*  Mb = mask + (size_t)b * SS;

    // Q fragments from global (fp16, pre-scaled): 4 k16-steps x 4 regs
    uint32_t qf[4][4];
    {
        const __half* Qb0 = Q + (size_t)(b * SS + q0 + wm + (lane >> 2)) * HH + h * DHH;
        const __half* Qb1 = Qb0 + 8 * HH;
        #pragma unroll
        for (int kt = 0; kt < 4; kt++) {
            int c = kt * 16 + 2 * (lane & 3);
            qf[kt][0] = *(const uint32_t*)(Qb0 + c);
            qf[kt][1] = *(const uint32_t*)(Qb1 + c);
            qf[kt][2] = *(const uint32_t*)(Qb0 + c + 8);
            qf[kt][3] = *(const uint32_t*)(Qb1 + c + 8);
        }
    }

    int krow = t >> 2, kwg = t & 3;       // K: 32 rows x 4 x 16 halfs
    int vrow = t >> 1, vwg = t & 1;       // Vt: 64 rows x 2 x 16 halfs

    // prologue: tile 0
    {
        cpa16(smem_u32(&Ks[0][krow][kwg * 8]),     Kb + (size_t)krow * HH + kwg * 16);
        cpa16(smem_u32(&Ks[0][krow][kwg * 8]) + 16, Kb + (size_t)krow * HH + kwg * 16 + 8);
        cpa16(smem_u32(&Vts[0][vrow][vwg * 8]),     Vb + (size_t)vrow * SS + vwg * 16);
        cpa16(smem_u32(&Vts[0][vrow][vwg * 8]) + 16, Vb + (size_t)vrow * SS + vwg * 16 + 8);
        cpa_commit();
    }

    float o[8][4];
    #pragma unroll
    for (int i = 0; i < 8; i++)
        #pragma unroll
        for (int j = 0; j < 4; j++) o[i][j] = 0.f;
    float m0 = -1e30f, m1 = -1e30f, l0 = 0.f, l1 = 0.f;

    const int NIT = SS / 32;
    #pragma unroll 1
    for (int it = 0; it < NIT; ++it) {
        int kb  = it * 32;
        int buf = it & 1;

        if (it + 1 < NIT) {
            int nb = buf ^ 1;
            cpa16(smem_u32(&Ks[nb][krow][kwg * 8]),
                  Kb + (size_t)(kb + 32 + krow) * HH + kwg * 16);
            cpa16(smem_u32(&Ks[nb][krow][kwg * 8]) + 16,
                  Kb + (size_t)(kb + 32 + krow) * HH + kwg * 16 + 8);
            cpa16(smem_u32(&Vts[nb][vrow][vwg * 8]),
                  Vb + (size_t)vrow * SS + kb + 32 + vwg * 16);
            cpa16(smem_u32(&Vts[nb][vrow][vwg * 8]) + 16,
                  Vb + (size_t)vrow * SS + kb + 32 + vwg * 16 + 8);
            cpa_commit();
            cpa_wait1();
        } else {
            cpa_wait0();
        }
        __syncthreads();

        // --- S = Q K^T : 4 k16-steps over D, 4 key-tiles of 8 ---
        float s[4][4];
        #pragma unroll
        for (int nt = 0; nt < 4; nt++)
            #pragma unroll
            for (int j = 0; j < 4; j++) s[nt][j] = 0.f;
        #pragma unroll
        for (int kt = 0; kt < 4; kt++) {
            int kk = kt * 8;
            #pragma unroll
            for (int nt = 0; nt < 4; nt++) {
                int kr = nt * 8 + (lane >> 2);
                uint32_t b0 = Ks[buf][kr][kk + (lane & 3)];
                uint32_t b1 = Ks[buf][kr][kk + 4 + (lane & 3)];
                mma16(s[nt], qf[kt], b0, b1);
            }
        }

        // --- online softmax (exp2 domain) ---
        float rmax0 = -1e30f, rmax1 = -1e30f;
        #pragma unroll
        for (int nt = 0; nt < 4; nt++) {
            int c = nt * 8 + 2 * (lane & 3);
            float2 mm = *(const float2*)(Mb + kb + c);
            float mv0 = mm.x * LOG2E, mv1 = mm.y * LOG2E;
            s[nt][0] += mv0; s[nt][1] += mv1;
            s[nt][2] += mv0; s[nt][3] += mv1;
            rmax0 = fmaxf(rmax0, fmaxf(s[nt][0], s[nt][1]));
            rmax1 = fmaxf(rmax1, fmaxf(s[nt][2], s[nt][3]));
        }
        rmax0 = fmaxf(rmax0, __shfl_xor_sync(0xffffffffu, rmax0, 1));
        rmax0 = fmaxf(rmax0, __shfl_xor_sync(0xffffffffu, rmax0, 2));
        rmax1 = fmaxf(rmax1, __shfl_xor_sync(0xffffffffu, rmax1, 1));
        rmax1 = fmaxf(rmax1, __shfl_xor_sync(0xffffffffu, rmax1, 2));

        float nm0 = fmaxf(m0, rmax0), nm1 = fmaxf(m1, rmax1);
        float a0 = fexp2f(m0 - nm0), a1 = fexp2f(m1 - nm1);
        m0 = nm0; m1 = nm1;

        float sum0 = 0.f, sum1 = 0.f;
        int r0 = wm + (lane >> 2);
        #pragma unroll
        for (int nt = 0; nt < 4; nt++) {
            float p0 = fexp2f(s[nt][0] - nm0);
            float p1 = fexp2f(s[nt][1] - nm0);
            float p2 = fexp2f(s[nt][2] - nm1);
            float p3 = fexp2f(s[nt][3] - nm1);
            sum0 += p0 + p1; sum1 += p2 + p3;
            int wd = nt * 4 + (lane & 3);   // key pair word
            Ps[r0][wd]     = h2u(__floats2half2_rn(p0, p1));
            Ps[r0 + 8][wd] = h2u(__floats2half2_rn(p2, p3));
        }
        sum0 += __shfl_xor_sync(0xffffffffu, sum0, 1);
        sum0 += __shfl_xor_sync(0xffffffffu, sum0, 2);
        sum1 += __shfl_xor_sync(0xffffffffu, sum1, 1);
        sum1 += __shfl_xor_sync(0xffffffffu, sum1, 2);
        l0 = l0 * a0 + sum0;
        l1 = l1 * a1 + sum1;

        #pragma unroll
        for (int dt = 0; dt < 8; dt++) {
            o[dt][0] *= a0; o[dt][1] *= a0;
            o[dt][2] *= a1; o[dt][3] *= a1;
        }
        __syncwarp();   // Ps rows are per-warp private

        // --- O += P V : 2 k16-steps over keys, 8 d-tiles ---
        #pragma unroll
        for (int kt = 0; kt < 2; kt++) {
            int kk = kt * 8;
            uint32_t af[4];
            af[0] = Ps[r0][kk + (lane & 3)];
            af[1] = Ps[r0 + 8][kk + (lane & 3)];
            af[2] = Ps[r0][kk + 4 + (lane & 3)];
            af[3] = Ps[r0 + 8][kk + 4 + (lane & 3)];
            #pragma unroll
            for (int dt = 0; dt < 8; dt++) {
                int dn = dt * 8 + (lane >> 2);
                uint32_t b0 = Vts[buf][dn][kk + (lane & 3)];
                uint32_t b1 = Vts[buf][dn][kk + 4 + (lane & 3)];
                mma16(o[dt], af, b0, b1);
            }
        }
        __syncthreads();
    }

    // write out: raw fp32 (residual) + fp16 (GEMM A path)
    float inv0 = 1.0f / l0, inv1 = 1.0f / l1;
    size_t gr = (size_t)(b * SS + q0 + wm + (lane >> 2));
    #pragma unroll
    for (int dt = 0; dt < 8; dt++) {
        int c = h * DHH + dt * 8 + 2 * (lane & 3);
        float v0 = o[dt][0] * inv0, v1 = o[dt][1] * inv0;
        float v2 = o[dt][2] * inv1, v3 = o[dt][3] * inv1;
        *(float2*)(out + gr * HH + c)       = make_float2(v0, v1);
        *(float2*)(out + (gr + 8) * HH + c) = make_float2(v2, v3);
        *(__half2*)(outr + gr * HH + c)       = __floats2half2_rn(v0, v1);
        *(__half2*)(outr + (gr + 8) * HH + c) = __floats2half2_rn(v2, v3);
    }
}

// ---------------------------------------------------------------------------
// Row LayerNorm over H=768, one block (256 threads) per row, shfl reductions.
// ---------------------------------------------------------------------------
__global__ void __launch_bounds__(256) layernorm_kernel(
    const float* __restrict__ y, const float* __restrict__ g,
    const float* __restrict__ be, float* __restrict__ out)
{
    __shared__ float part[8];
    __shared__ float bc0, bc1;
    int row = blockIdx.x;
    const float* yr = y + (size_t)row * HH;
    int t = threadIdx.x, w = t >> 5, lane = t & 31;

    float x0 = yr[t], x1 = yr[t + 256], x2 = yr[t + 512];
    float s = x0 + x1 + x2;
    #pragma unroll
    for (int o = 16; o >= 1; o >>= 1) s += __shfl_xor_sync(0xffffffffu, s, o);
    if (lane == 0) part[w] = s;
    __syncthreads();
    if (t == 0) {
        float tot = 0.f;
        #pragma unroll
        for (int i = 0; i < 8; i++) tot += part[i];
        bc0 = tot;
    }
    __syncthreads();
    float mu = bc0 * (1.0f / HH);
    float d0 = x0 - mu, d1 = x1 - mu, d2 = x2 - mu;
    float sq = d0 * d0 + d1 * d1 + d2 * d2;
    #pragma unroll
    for (int o = 16; o >= 1; o >>= 1) sq += __shfl_xor_sync(0xffffffffu, sq, o);
    if (lane == 0) part[w] = sq;
    __syncthreads();
    if (t == 0) {
        float tot = 0.f;
        #pragma unroll
        for (int i = 0; i < 8; i++) tot += part[i];
        bc1 = tot;
    }
    __syncthreads();
    float rstd = rsqrtf(bc1 * (1.0f / HH) + 1e-12f);
    float* o = out + (size_t)row * HH;
    o[t]       = d0 * rstd * g[t]       + be[t];
    o[t + 256] = d1 * rstd * g[t + 256] + be[t + 256];
    o[t + 512] = d2 * rstd * g[t + 512] + be[t + 512];
}

// ---------------------------------------------------------------------------
extern "C" void kernel_launch(void* const* d_in, const int* in_sizes, int n_in,
                              void* d_out, int out_size)
{
    const float* hs   = (const float*)d_in[0];
    const float* mask = (const float*)d_in[1];
    const float* wq = (const float*)d_in[2];  const float* bq = (const float*)d_in[3];
    const float* wk = (const float*)d_in[4];  const float* bk = (const float*)d_in[5];
    const float* wv = (const float*)d_in[6];  const float* bv = (const float*)d_in[7];
    const float* afw = (const float*)d_in[8]; const float* afb = (const float*)d_in[9];
    const float* asw = (const float*)d_in[10];const float* asb = (const float*)d_in[11];
    const float* wi = (const float*)d_in[12]; const float* bi = (const float*)d_in[13];
    const float* wo = (const float*)d_in[14]; const float* bo = (const float*)d_in[15];
    const float* lg = (const float*)d_in[16]; const float* lb = (const float*)d_in[17];
    float* out = (float*)d_out;

    __half *qh, *kh, *vth, *attnrh, *adpth, *attn2rh, *interh;
    __half *hsh, *wqh, *wkh, *wvh, *afwh, *aswh, *wih, *woh;
    float *attn, *attn2, *y;
    cudaGetSymbolAddress((void**)&qh,      g_qh);
    cudaGetSymbolAddress((void**)&kh,      g_kh);
    cudaGetSymbolAddress((void**)&vth,     g_vth);
    cudaGetSymbolAddress((void**)&attn,    g_attn);
    cudaGetSymbolAddress((void**)&attnrh,  g_attnrh);
    cudaGetSymbolAddress((void**)&adpth,   g_adpth);
    cudaGetSymbolAddress((void**)&attn2,   g_attn2);
    cudaGetSymbolAddress((void**)&attn2rh, g_attn2rh);
    cudaGetSymbolAddress((void**)&interh,  g_interh);
    cudaGetSymbolAddress((void**)&y,       g_y);
    cudaGetSymbolAddress((void**)&hsh,     g_hsh);
    cudaGetSymbolAddress((void**)&wqh,     g_wqh);
    cudaGetSymbolAddress((void**)&wkh,     g_wkh);
    cudaGetSymbolAddress((void**)&wvh,     g_wvh);
    cudaGetSymbolAddress((void**)&afwh,    g_afwh);
    cudaGetSymbolAddress((void**)&aswh,    g_aswh);
    cudaGetSymbolAddress((void**)&wih,     g_wih);
    cudaGetSymbolAddress((void**)&woh,     g_woh);

    cudaFuncSetAttribute(tgemm_qkv,
        cudaFuncAttributeMaxDynamicSharedMemorySize, GSM_BYTES);
    cudaFuncSetAttribute(tgemm_cp<2, 2>,
        cudaFuncAttributeMaxDynamicSharedMemorySize, GSM_BYTES);
    cudaFuncSetAttribute(tgemm_cp<1, 1>,
        cudaFuncAttributeMaxDynamicSharedMemorySize, GSM_BYTES);
    cudaFuncSetAttribute(tgemm_cp<2, 0>,
        cudaFuncAttributeMaxDynamicSharedMemorySize, GSM_BYTES);

    // 0) round operands to fp16
    round_prep<<<1024, 256>>>(
        (const float4*)hs, (const float4*)wq, (const float4*)wk, (const float4*)wv,
        (const float4*)afw, (const float4*)asw, (const float4*)wi, (const float4*)wo,
        hsh, wqh, wkh, wvh, afwh, aswh, wih, woh);

    // 1) fused QKV projection (fp16 outputs; Q pre-scaled; V transposed)
    tgemm_qkv<<<dim3(18, 32), 256, GSM_BYTES>>>(
        hsh, wqh, wkh, wvh, bq, bk, bv, qh, kh, vth);

    // 2) attention
    flash_attn_h<<<dim3(SS / 64, BB * NHH), 128>>>(
        qh, kh, vth, mask, attn, attnrh);

    // 3) adapter bottleneck
    adapter_down<<<MM / 32, 128>>>(attnrh, afwh, afb, adpth);
    tgemm_cp<2, 2><<<dim3(6, 32), 256, GSM_BYTES>>>(
        MM, HH, ADD, adpth, aswh, asb, attn, attn2, attn2rh);

    // 4) FFN
    tgemm_cp<1, 1><<<dim3(24, 32), 256, GSM_BYTES>>>(
        MM, FFF, HH, attn2rh, wih, bi, nullptr, nullptr, interh);
    tgemm_cp<2, 0><<<dim3(6, 32), 256, GSM_BYTES>>>(
        MM, HH, FFF, interh, woh, bo, attn2, y, nullptr);

    // 5) LayerNorm -> output
    layernorm_kernel<<<MM, 256>>>(y, lg, lb, out);
}